// round 4
// baseline (speedup 1.0000x reference)
#include <cuda_runtime.h>
#include <cuda_bf16.h>
#include <stdint.h>

#define NB      8
#define SNEW    16
#define DM      2048
#define NH      16
#define HD      128
#define PAST    4096
#define MR      128
#define QSCALE  0.08838834764831843f

// ---------------- device scratch (no allocations allowed) ----------------
__device__ __nv_bfloat16 g_qh[MR * DM];
__device__ __nv_bfloat16 g_ql[MR * DM];
__device__ float         g_knew[MR * DM];
__device__ float         g_vnew[MR * DM];
__device__ float         g_attn[MR * DM];

// ---------------- helpers ----------------
__device__ __forceinline__ void cp16(void* s, const void* g) {
    uint32_t sa = (uint32_t)__cvta_generic_to_shared(s);
    asm volatile("cp.async.cg.shared.global [%0], [%1], 16;\n" :: "r"(sa), "l"(g));
}
__device__ __forceinline__ void cpcommit() { asm volatile("cp.async.commit_group;\n"); }
template <int N>
__device__ __forceinline__ void cpwait() { asm volatile("cp.async.wait_group %0;\n" :: "n"(N)); }

__device__ __forceinline__ void mmabf(float* c, const uint32_t* a, const uint32_t* b) {
    asm volatile(
        "mma.sync.aligned.m16n8k16.row.col.f32.bf16.bf16.f32 "
        "{%0,%1,%2,%3},{%4,%5,%6,%7},{%8,%9},{%0,%1,%2,%3};"
        : "+f"(c[0]), "+f"(c[1]), "+f"(c[2]), "+f"(c[3])
        : "r"(a[0]), "r"(a[1]), "r"(a[2]), "r"(a[3]), "r"(b[0]), "r"(b[1]));
}
__device__ __forceinline__ uint32_t ldu32(const __nv_bfloat16* p) {
    return *reinterpret_cast<const uint32_t*>(p);
}
__device__ __forceinline__ void split2(float f, __nv_bfloat16* hp, __nv_bfloat16* lp) {
    __nv_bfloat16 h = __float2bfloat16(f);
    *hp = h;
    *lp = __float2bfloat16(f - __bfloat162float(h));
}

// ---------------------------------------------------------------------------
// GEMM core: C[128 x (64-col tile)] = A[128 x 2048] @ W[2048 x 2048]
// 256 threads = 8 warps (4 M x 2 N), warp tile 32x32, BK=32, double buffered
// ---------------------------------------------------------------------------
#define GP 34   // smem pitch (bf16 elems) for [row][k] frag arrays
struct GemmSmem {
    float stA[2][MR * 32];
    float stB[2][32 * 64];
    __nv_bfloat16 Ah[MR * GP], Al[MR * GP];
    __nv_bfloat16 Bh[64 * GP], Bl[64 * GP];
};

__device__ __forceinline__ void gemm_core(const float* __restrict__ A,
                                          const float* __restrict__ W,
                                          GemmSmem* S, float acc[2][4][4], int nb) {
    const int tid = threadIdx.x, lane = tid & 31;
    const int warpM = (tid >> 5) & 3, warpN = tid >> 7;

    #pragma unroll
    for (int i = 0; i < 4; i++) { int idx = tid + i * 256; int r = idx >> 3, c = (idx & 7) * 4;
        cp16(&S->stA[0][r * 32 + c], A + (size_t)r * DM + c); }
    #pragma unroll
    for (int i = 0; i < 2; i++) { int idx = tid + i * 256; int kr = idx >> 4, c = (idx & 15) * 4;
        cp16(&S->stB[0][kr * 64 + c], W + (size_t)kr * DM + nb * 64 + c); }
    cpcommit();

    for (int kt = 0; kt < 64; kt++) {
        int cur = kt & 1;
        if (kt < 63) {
            int nx = cur ^ 1, kb = (kt + 1) * 32;
            #pragma unroll
            for (int i = 0; i < 4; i++) { int idx = tid + i * 256; int r = idx >> 3, c = (idx & 7) * 4;
                cp16(&S->stA[nx][r * 32 + c], A + (size_t)r * DM + kb + c); }
            #pragma unroll
            for (int i = 0; i < 2; i++) { int idx = tid + i * 256; int kr = idx >> 4, c = (idx & 15) * 4;
                cp16(&S->stB[nx][kr * 64 + c], W + (size_t)(kb + kr) * DM + nb * 64 + c); }
            cpcommit();
            cpwait<1>();
        } else {
            cpwait<0>();
        }
        __syncthreads();

        #pragma unroll
        for (int i = 0; i < 16; i++) { int idx = i * 256 + tid; int r = idx >> 5, k = idx & 31;
            split2(S->stA[cur][idx], &S->Ah[r * GP + k], &S->Al[r * GP + k]); }
        #pragma unroll
        for (int i = 0; i < 8; i++) { int idx = i * 256 + tid; int kr = idx >> 6, n = idx & 63;
            split2(S->stB[cur][idx], &S->Bh[n * GP + kr], &S->Bl[n * GP + kr]); }
        __syncthreads();

        #pragma unroll
        for (int ks = 0; ks < 2; ks++) {
            const int kk = ks * 16 + (lane & 3) * 2, r0 = lane >> 2;
            uint32_t ah[2][4], al[2][4];
            #pragma unroll
            for (int mi = 0; mi < 2; mi++) {
                int r = warpM * 32 + mi * 16 + r0;
                ah[mi][0] = ldu32(&S->Ah[r * GP + kk]);
                ah[mi][1] = ldu32(&S->Ah[(r + 8) * GP + kk]);
                ah[mi][2] = ldu32(&S->Ah[r * GP + kk + 8]);
                ah[mi][3] = ldu32(&S->Ah[(r + 8) * GP + kk + 8]);
                al[mi][0] = ldu32(&S->Al[r * GP + kk]);
                al[mi][1] = ldu32(&S->Al[(r + 8) * GP + kk]);
                al[mi][2] = ldu32(&S->Al[r * GP + kk + 8]);
                al[mi][3] = ldu32(&S->Al[(r + 8) * GP + kk + 8]);
            }
            #pragma unroll
            for (int ni = 0; ni < 4; ni++) {
                int n = warpN * 32 + ni * 8 + r0;
                uint32_t bh[2], bl[2];
                bh[0] = ldu32(&S->Bh[n * GP + kk]); bh[1] = ldu32(&S->Bh[n * GP + kk + 8]);
                bl[0] = ldu32(&S->Bl[n * GP + kk]); bl[1] = ldu32(&S->Bl[n * GP + kk + 8]);
                #pragma unroll
                for (int mi = 0; mi < 2; mi++) {
                    mmabf(acc[mi][ni], ah[mi], bh);
                    mmabf(acc[mi][ni], ah[mi], bl);
                    mmabf(acc[mi][ni], al[mi], bh);
                }
            }
        }
        __syncthreads();
    }
}

__global__ void __launch_bounds__(256, 1)
gemm_qkv_kernel(const float* __restrict__ x,
                const float* __restrict__ Wq, const float* __restrict__ bq,
                const float* __restrict__ Wk, const float* __restrict__ bk,
                const float* __restrict__ Wv, const float* __restrict__ bv) {
    extern __shared__ char smraw[];
    GemmSmem* S = (GemmSmem*)smraw;
    const int z = blockIdx.z, nb = blockIdx.x;
    const float* W    = (z == 0) ? Wq : ((z == 1) ? Wk : Wv);
    const float* bias = (z == 0) ? bq : ((z == 1) ? bk : bv);

    float acc[2][4][4] = {};
    gemm_core(x, W, S, acc, nb);

    const int lane = threadIdx.x & 31, warpM = (threadIdx.x >> 5) & 3, warpN = threadIdx.x >> 7;
    #pragma unroll
    for (int mi = 0; mi < 2; mi++) {
        #pragma unroll
        for (int ni = 0; ni < 4; ni++) {
            int rb = warpM * 32 + mi * 16 + (lane >> 2);
            int cb = nb * 64 + warpN * 32 + ni * 8 + (lane & 3) * 2;
            #pragma unroll
            for (int ci = 0; ci < 4; ci++) {
                int m = rb + ((ci & 2) ? 8 : 0);
                int n = cb + (ci & 1);
                float v = acc[mi][ni][ci] + bias[n];
                int idx = (((m >> 4) * NH + (n >> 7)) * SNEW + (m & 15)) * HD + (n & 127);
                if (z == 0)      { v *= QSCALE; split2(v, &g_qh[idx], &g_ql[idx]); }
                else if (z == 1) { g_knew[idx] = v; }
                else             { g_vnew[idx] = v; }
            }
        }
    }
}

__global__ void __launch_bounds__(256, 1)
gemm_o_kernel(const float* __restrict__ Wo, const float* __restrict__ bo,
              float* __restrict__ out) {
    extern __shared__ char smraw[];
    GemmSmem* S = (GemmSmem*)smraw;
    const int nb = blockIdx.x;

    float acc[2][4][4] = {};
    gemm_core(g_attn, Wo, S, acc, nb);

    const int lane = threadIdx.x & 31, warpM = (threadIdx.x >> 5) & 3, warpN = threadIdx.x >> 7;
    #pragma unroll
    for (int mi = 0; mi < 2; mi++) {
        #pragma unroll
        for (int ni = 0; ni < 4; ni++) {
            int rb = warpM * 32 + mi * 16 + (lane >> 2);
            int cb = nb * 64 + warpN * 32 + ni * 8 + (lane & 3) * 2;
            #pragma unroll
            for (int ci = 0; ci < 4; ci++) {
                int m = rb + ((ci & 2) ? 8 : 0);
                int n = cb + (ci & 1);
                out[(size_t)m * DM + n] = acc[mi][ni][ci] + bo[n];
            }
        }
    }
}

// ---------------------------------------------------------------------------
// Attention: one CTA per (b,h). Flash online softmax over 65 key tiles.
// ---------------------------------------------------------------------------
#define KP 132   // pitch for [row][d] arrays (keys/q: 128 d + pad)
#define VP 72    // pitch for [d][key] / [q][key] arrays (64 keys + pad)
struct AttnSmem {
    float stK[2][64 * HD];
    float stV[2][64 * HD];
    __nv_bfloat16 Kh[64 * KP], Kl[64 * KP];
    __nv_bfloat16 Vh[HD * VP], Vl[HD * VP];
    __nv_bfloat16 Qh[SNEW * KP], Ql[SNEW * KP];
    float Ss[SNEW * 68];
    __nv_bfloat16 Ph[SNEW * VP], Pl[SNEW * VP];
    float mrow[SNEW], lrow[SNEW], arow[SNEW];
};

__global__ void __launch_bounds__(256, 1)
attn_kernel(const float* __restrict__ kc, const float* __restrict__ vc) {
    extern __shared__ char smraw[];
    AttnSmem* S = (AttnSmem*)smraw;
    const int bh = blockIdx.x;
    const int tid = threadIdx.x, lane = tid & 31, wid = tid >> 5;

    const float* kbase = kc + (size_t)bh * PAST * HD;
    const float* vbase = vc + (size_t)bh * PAST * HD;
    const float* knew  = g_knew + (size_t)bh * SNEW * HD;
    const float* vnew  = g_vnew + (size_t)bh * SNEW * HD;

    #pragma unroll
    for (int i = 0; i < 8; i++) {
        int idx = i * 256 + tid; int s = idx >> 7, d = idx & 127;
        S->Qh[s * KP + d] = g_qh[(size_t)bh * SNEW * HD + idx];
        S->Ql[s * KP + d] = g_ql[(size_t)bh * SNEW * HD + idx];
    }
    if (tid < SNEW) { S->mrow[tid] = -1e30f; S->lrow[tid] = 0.f; }

    float o[2][4] = {};

    auto loadKV = [&](int ti, int buf) {
        const float* kp; const float* vp; int nf4;
        if (ti < 64) { kp = kbase + (size_t)ti * 64 * HD; vp = vbase + (size_t)ti * 64 * HD; nf4 = 64 * 32; }
        else         { kp = knew; vp = vnew; nf4 = SNEW * 32; }
        #pragma unroll
        for (int i = 0; i < 8; i++) {
            int idx = i * 256 + tid;
            if (idx < nf4) {
                cp16(&S->stK[buf][idx * 4], kp + idx * 4);
                cp16(&S->stV[buf][idx * 4], vp + idx * 4);
            }
        }
    };

    const int NT = 65;
    loadKV(0, 0);
    cpcommit();

    for (int ti = 0; ti < NT; ti++) {
        int cur = ti & 1;
        if (ti + 1 < NT) { loadKV(ti + 1, cur ^ 1); cpcommit(); cpwait<1>(); }
        else             { cpwait<0>(); }
        __syncthreads();

        const int nk = (ti < 64) ? 64 : SNEW;

        // convert fp32 -> bf16 hi/lo; V transposed to [d][key]
        #pragma unroll
        for (int i = 0; i < 32; i++) {
            int idx = i * 256 + tid; int key = idx >> 7, d = idx & 127;
            float fk = (key < nk) ? S->stK[cur][idx] : 0.f;
            float fv = (key < nk) ? S->stV[cur][idx] : 0.f;
            split2(fk, &S->Kh[key * KP + d], &S->Kl[key * KP + d]);
            split2(fv, &S->Vh[d * VP + key], &S->Vl[d * VP + key]);
        }
        __syncthreads();

        // --- QK^T: warp w -> score columns [8w, 8w+8), bf16x3 ---
        {
            float sacc[4] = {0.f, 0.f, 0.f, 0.f};
            const int n = wid * 8 + (lane >> 2);
            const int r = lane >> 2, kkb = (lane & 3) * 2;
            #pragma unroll
            for (int ks = 0; ks < 8; ks++) {
                int kk = ks * 16 + kkb;
                uint32_t ah[4], al[4], bh2[2], bl2[2];
                ah[0] = ldu32(&S->Qh[r * KP + kk]);       ah[1] = ldu32(&S->Qh[(r + 8) * KP + kk]);
                ah[2] = ldu32(&S->Qh[r * KP + kk + 8]);   ah[3] = ldu32(&S->Qh[(r + 8) * KP + kk + 8]);
                al[0] = ldu32(&S->Ql[r * KP + kk]);       al[1] = ldu32(&S->Ql[(r + 8) * KP + kk]);
                al[2] = ldu32(&S->Ql[r * KP + kk + 8]);   al[3] = ldu32(&S->Ql[(r + 8) * KP + kk + 8]);
                bh2[0] = ldu32(&S->Kh[n * KP + kk]);      bh2[1] = ldu32(&S->Kh[n * KP + kk + 8]);
                bl2[0] = ldu32(&S->Kl[n * KP + kk]);      bl2[1] = ldu32(&S->Kl[n * KP + kk + 8]);
                mmabf(sacc, ah, bh2);
                mmabf(sacc, ah, bl2);
                mmabf(sacc, al, bh2);
            }
            const int cn = (lane & 3) * 2;
            #pragma unroll
            for (int ci = 0; ci < 4; ci++) {
                int row = r + ((ci & 2) ? 8 : 0);
                int col = wid * 8 + cn + (ci & 1);
                float v = sacc[ci];
                if (ti == 64 && (col > row || col >= SNEW)) v = -1e30f;
                S->Ss[row * 68 + col] = v;
            }
        }
        __syncthreads();

        // --- online softmax: warp w handles rows 2w, 2w+1 ---
        #pragma unroll
        for (int rr = 0; rr < 2; rr++) {
            int row = wid * 2 + rr;
            float s0 = S->Ss[row * 68 + lane];
            float s1 = S->Ss[row * 68 + lane + 32];
            float mx = fmaxf(s0, s1);
            #pragma unroll
            for (int off = 16; off > 0; off >>= 1)
                mx = fmaxf(mx, __shfl_xor_sync(0xffffffffu, mx, off));
            float m_old = S->mrow[row];
            float m_new = fmaxf(m_old, mx);
            float p0 = __expf(s0 - m_new), p1 = __expf(s1 - m_new);
            float ps = p0 + p1;
            #pragma unroll
            for (int off = 16; off > 0; off >>= 1)
                ps += __shfl_xor_sync(0xffffffffu, ps, off);
            if (lane == 0) {
                float alpha = __expf(m_old - m_new);
                S->arow[row] = alpha;
                S->lrow[row] = S->lrow[row] * alpha + ps;
                S->mrow[row] = m_new;
            }
            split2(p0, &S->Ph[row * VP + lane],      &S->Pl[row * VP + lane]);
            split2(p1, &S->Ph[row * VP + lane + 32], &S->Pl[row * VP + lane + 32]);
        }
        __syncthreads();

        // --- rescale O, then PV: warp w -> d columns [16w, 16w+16) ---
        {
            const int r = lane >> 2;
            float a0 = S->arow[r], a1 = S->arow[r + 8];
            #pragma unroll
            for (int ni = 0; ni < 2; ni++) {
                o[ni][0] *= a0; o[ni][1] *= a0;
                o[ni][2] *= a1; o[ni][3] *= a1;
            }
            const int kkb = (lane & 3) * 2;
            #pragma unroll
            for (int ks = 0; ks < 4; ks++) {
                int kk = ks * 16 + kkb;
                uint32_t ah[4], al[4];
                ah[0] = ldu32(&S->Ph[r * VP + kk]);       ah[1] = ldu32(&S->Ph[(r + 8) * VP + kk]);
                ah[2] = ldu32(&S->Ph[r * VP + kk + 8]);   ah[3] = ldu32(&S->Ph[(r + 8) * VP + kk + 8]);
                al[0] = ldu32(&S->Pl[r * VP + kk]);       al[1] = ldu32(&S->Pl[(r + 8) * VP + kk]);
                al[2] = ldu32(&S->Pl[r * VP + kk + 8]);   al[3] = ldu32(&S->Pl[(r + 8) * VP + kk + 8]);
                #pragma unroll
                for (int ni = 0; ni < 2; ni++) {
                    int n = wid * 16 + ni * 8 + r;
                    uint32_t bh2[2], bl2[2];
                    bh2[0] = ldu32(&S->Vh[n * VP + kk]);  bh2[1] = ldu32(&S->Vh[n * VP + kk + 8]);
                    bl2[0] = ldu32(&S->Vl[n * VP + kk]);  bl2[1] = ldu32(&S->Vl[n * VP + kk + 8]);
                    mmabf(o[ni], ah, bh2);
                    mmabf(o[ni], ah, bl2);
                    mmabf(o[ni], al, bh2);
                }
            }
        }
    }
    __syncthreads();

    // epilogue: normalize and write [ (b*16+q) ][ h*128 + d ] to g_attn
    {
        const int b = bh >> 4, h = bh & 15;
        const int r = lane >> 2, cn = (lane & 3) * 2;
        float li0 = 1.f / S->lrow[r], li1 = 1.f / S->lrow[r + 8];
        #pragma unroll
        for (int ni = 0; ni < 2; ni++) {
            #pragma unroll
            for (int ci = 0; ci < 4; ci++) {
                int row = r + ((ci & 2) ? 8 : 0);
                int col = wid * 16 + ni * 8 + cn + (ci & 1);
                float v = o[ni][ci] * ((ci & 2) ? li1 : li0);
                g_attn[(size_t)(b * SNEW + row) * DM + h * HD + col] = v;
            }
        }
    }
}

// ---------------------------------------------------------------------------
extern "C" void kernel_launch(void* const* d_in, const int* in_sizes, int n_in,
                              void* d_out, int out_size) {
    const float* x  = (const float*)d_in[0];
    const float* kc = (const float*)d_in[1];
    const float* vc = (const float*)d_in[2];
    const float* Wq = (const float*)d_in[3];
    const float* bq = (const float*)d_in[4];
    const float* Wk = (const float*)d_in[5];
    const float* bk = (const float*)d_in[6];
    const float* Wv = (const float*)d_in[7];
    const float* bv = (const float*)d_in[8];
    const float* Wo = (const float*)d_in[9];
    const float* bo = (const float*)d_in[10];
    float* out = (float*)d_out;

    cudaFuncSetAttribute(gemm_qkv_kernel, cudaFuncAttributeMaxDynamicSharedMemorySize, (int)sizeof(GemmSmem));
    cudaFuncSetAttribute(gemm_o_kernel,   cudaFuncAttributeMaxDynamicSharedMemorySize, (int)sizeof(GemmSmem));
    cudaFuncSetAttribute(attn_kernel,     cudaFuncAttributeMaxDynamicSharedMemorySize, (int)sizeof(AttnSmem));

    dim3 gq(32, 1, 3);
    gemm_qkv_kernel<<<gq, 256, sizeof(GemmSmem)>>>(x, Wq, bq, Wk, bk, Wv, bv);
    attn_kernel<<<128, 256, sizeof(AttnSmem)>>>(kc, vc);
    gemm_o_kernel<<<32, 256, sizeof(GemmSmem)>>>(Wo, bo, out);
}

// round 6
// speedup vs baseline: 1.3400x; 1.3400x over previous
#include <cuda_runtime.h>
#include <cuda_bf16.h>
#include <stdint.h>

#define NB      8
#define SNEW    16
#define DM      2048
#define NH      16
#define HD      128
#define PAST    4096
#define MR      128
#define QSCALE  0.08838834764831843f

// ---------------- device scratch (no allocations allowed) ----------------
__device__ __nv_bfloat16 g_qh[MR * DM];
__device__ __nv_bfloat16 g_ql[MR * DM];
__device__ float         g_knew[MR * DM];
__device__ float         g_vnew[MR * DM];
__device__ float         g_attn[MR * DM];
__device__ float         g_part[3 * 8 * MR * DM];   // split-K partials (25 MB)

// ---------------- helpers ----------------
__device__ __forceinline__ void cp16(void* s, const void* g) {
    uint32_t sa = (uint32_t)__cvta_generic_to_shared(s);
    asm volatile("cp.async.cg.shared.global [%0], [%1], 16;\n" :: "r"(sa), "l"(g));
}
__device__ __forceinline__ void cpcommit() { asm volatile("cp.async.commit_group;\n"); }
template <int N>
__device__ __forceinline__ void cpwait() { asm volatile("cp.async.wait_group %0;\n" :: "n"(N)); }

__device__ __forceinline__ void mmabf(float* c, const uint32_t* a, const uint32_t* b) {
    asm volatile(
        "mma.sync.aligned.m16n8k16.row.col.f32.bf16.bf16.f32 "
        "{%0,%1,%2,%3},{%4,%5,%6,%7},{%8,%9},{%0,%1,%2,%3};"
        : "+f"(c[0]), "+f"(c[1]), "+f"(c[2]), "+f"(c[3])
        : "r"(a[0]), "r"(a[1]), "r"(a[2]), "r"(a[3]), "r"(b[0]), "r"(b[1]));
}
__device__ __forceinline__ uint32_t ldu32(const __nv_bfloat16* p) {
    return *reinterpret_cast<const uint32_t*>(p);
}
__device__ __forceinline__ void split2(float f, __nv_bfloat16* hp, __nv_bfloat16* lp) {
    __nv_bfloat16 h = __float2bfloat16(f);
    *hp = h;
    *lp = __float2bfloat16(f - __bfloat162float(h));
}
__device__ __forceinline__ uint32_t packbf(__nv_bfloat16 a, __nv_bfloat16 b) {
    uint16_t ua = *reinterpret_cast<uint16_t*>(&a);
    uint16_t ub = *reinterpret_cast<uint16_t*>(&b);
    return (uint32_t)ua | ((uint32_t)ub << 16);
}
// split fp32 -> packed (hi pair, lo pair) not needed; do per-element

// ---------------------------------------------------------------------------
// Split-K GEMM partial: C_part[128 x 64tile] = A[128, 256-slice] @ W[slice, 64]
// 256 threads = 8 warps (4 M x 2 N), warp tile 32x32, BK=32, double buffered,
// 8 K-iterations per CTA.
// ---------------------------------------------------------------------------
#define GP 34
struct GemmSmem {
    float stA[2][MR * 32];
    float stB[2][32 * 64];
    __nv_bfloat16 Ah[MR * GP], Al[MR * GP];
    __nv_bfloat16 Bh[64 * GP], Bl[64 * GP];
};

__device__ __forceinline__ void gemm_core_part(const float* __restrict__ A,
                                               const float* __restrict__ W,
                                               GemmSmem* S, float acc[2][4][4],
                                               int nb, int k0) {
    const int tid = threadIdx.x, lane = tid & 31;
    const int warpM = (tid >> 5) & 3, warpN = tid >> 7;

    #pragma unroll
    for (int i = 0; i < 4; i++) { int idx = tid + i * 256; int r = idx >> 3, c = (idx & 7) * 4;
        cp16(&S->stA[0][r * 32 + c], A + (size_t)r * DM + k0 + c); }
    #pragma unroll
    for (int i = 0; i < 2; i++) { int idx = tid + i * 256; int kr = idx >> 4, c = (idx & 15) * 4;
        cp16(&S->stB[0][kr * 64 + c], W + (size_t)(k0 + kr) * DM + nb * 64 + c); }
    cpcommit();

    #pragma unroll 1
    for (int kt = 0; kt < 8; kt++) {
        int cur = kt & 1;
        if (kt < 7) {
            int nx = cur ^ 1, kb = k0 + (kt + 1) * 32;
            #pragma unroll
            for (int i = 0; i < 4; i++) { int idx = tid + i * 256; int r = idx >> 3, c = (idx & 7) * 4;
                cp16(&S->stA[nx][r * 32 + c], A + (size_t)r * DM + kb + c); }
            #pragma unroll
            for (int i = 0; i < 2; i++) { int idx = tid + i * 256; int kr = idx >> 4, c = (idx & 15) * 4;
                cp16(&S->stB[nx][kr * 64 + c], W + (size_t)(kb + kr) * DM + nb * 64 + c); }
            cpcommit();
            cpwait<1>();
        } else {
            cpwait<0>();
        }
        __syncthreads();

        #pragma unroll
        for (int i = 0; i < 16; i++) { int idx = i * 256 + tid; int r = idx >> 5, k = idx & 31;
            split2(S->stA[cur][idx], &S->Ah[r * GP + k], &S->Al[r * GP + k]); }
        #pragma unroll
        for (int i = 0; i < 8; i++) { int idx = i * 256 + tid; int kr = idx >> 6, n = idx & 63;
            split2(S->stB[cur][idx], &S->Bh[n * GP + kr], &S->Bl[n * GP + kr]); }
        __syncthreads();

        #pragma unroll
        for (int ks = 0; ks < 2; ks++) {
            const int kk = ks * 16 + (lane & 3) * 2, r0 = lane >> 2;
            uint32_t ah[2][4], al[2][4];
            #pragma unroll
            for (int mi = 0; mi < 2; mi++) {
                int r = warpM * 32 + mi * 16 + r0;
                ah[mi][0] = ldu32(&S->Ah[r * GP + kk]);
                ah[mi][1] = ldu32(&S->Ah[(r + 8) * GP + kk]);
                ah[mi][2] = ldu32(&S->Ah[r * GP + kk + 8]);
                ah[mi][3] = ldu32(&S->Ah[(r + 8) * GP + kk + 8]);
                al[mi][0] = ldu32(&S->Al[r * GP + kk]);
                al[mi][1] = ldu32(&S->Al[(r + 8) * GP + kk]);
                al[mi][2] = ldu32(&S->Al[r * GP + kk + 8]);
                al[mi][3] = ldu32(&S->Al[(r + 8) * GP + kk + 8]);
            }
            #pragma unroll
            for (int ni = 0; ni < 4; ni++) {
                int n = warpN * 32 + ni * 8 + r0;
                uint32_t bh[2], bl[2];
                bh[0] = ldu32(&S->Bh[n * GP + kk]); bh[1] = ldu32(&S->Bh[n * GP + kk + 8]);
                bl[0] = ldu32(&S->Bl[n * GP + kk]); bl[1] = ldu32(&S->Bl[n * GP + kk + 8]);
                #pragma unroll
                for (int mi = 0; mi < 2; mi++) {
                    mmabf(acc[mi][ni], ah[mi], bh);
                    mmabf(acc[mi][ni], ah[mi], bl);
                    mmabf(acc[mi][ni], al[mi], bh);
                }
            }
        }
        __syncthreads();
    }
}

__device__ __forceinline__ void store_partial(float acc[2][4][4], float* dst, int nb) {
    const int lane = threadIdx.x & 31, warpM = (threadIdx.x >> 5) & 3, warpN = threadIdx.x >> 7;
    #pragma unroll
    for (int mi = 0; mi < 2; mi++) {
        #pragma unroll
        for (int ni = 0; ni < 4; ni++) {
            int rb = warpM * 32 + mi * 16 + (lane >> 2);
            int cb = nb * 64 + warpN * 32 + ni * 8 + (lane & 3) * 2;
            #pragma unroll
            for (int ci = 0; ci < 4; ci++) {
                int m = rb + ((ci & 2) ? 8 : 0);
                int n = cb + (ci & 1);
                dst[(size_t)m * DM + n] = acc[mi][ni][ci];
            }
        }
    }
}

__global__ void __launch_bounds__(256, 2)
qkv_partial_kernel(const float* __restrict__ x,
                   const float* __restrict__ Wq, const float* __restrict__ Wk,
                   const float* __restrict__ Wv) {
    extern __shared__ char smraw[];
    GemmSmem* S = (GemmSmem*)smraw;
    const int nb = blockIdx.x, kc = blockIdx.y, z = blockIdx.z;
    const float* W = (z == 0) ? Wq : ((z == 1) ? Wk : Wv);
    float acc[2][4][4] = {};
    gemm_core_part(x, W, S, acc, nb, kc * 256);
    store_partial(acc, g_part + (size_t)(z * 8 + kc) * MR * DM, nb);
}

__global__ void __launch_bounds__(256)
qkv_reduce_kernel(const float* __restrict__ bq, const float* __restrict__ bk,
                  const float* __restrict__ bv) {
    const int z = blockIdx.y;
    const int idx = blockIdx.x * 256 + threadIdx.x;   // 0 .. 128*2048-1
    const int m = idx >> 11, n = idx & 2047;
    float s = 0.f;
    #pragma unroll
    for (int kc = 0; kc < 8; kc++)
        s += g_part[(size_t)(z * 8 + kc) * MR * DM + idx];
    const int qidx = (((m >> 4) * NH + (n >> 7)) * SNEW + (m & 15)) * HD + (n & 127);
    if (z == 0) {
        s = (s + bq[n]) * QSCALE;
        split2(s, &g_qh[qidx], &g_ql[qidx]);
    } else if (z == 1) {
        g_knew[qidx] = s + bk[n];
    } else {
        g_vnew[qidx] = s + bv[n];
    }
}

__global__ void __launch_bounds__(256, 2)
o_partial_kernel(const float* __restrict__ Wo) {
    extern __shared__ char smraw[];
    GemmSmem* S = (GemmSmem*)smraw;
    const int nb = blockIdx.x, kc = blockIdx.y;
    float acc[2][4][4] = {};
    gemm_core_part(g_attn, Wo, S, acc, nb, kc * 256);
    store_partial(acc, g_part + (size_t)kc * MR * DM, nb);
}

__global__ void __launch_bounds__(256)
o_reduce_kernel(const float* __restrict__ bo, float* __restrict__ out) {
    const int idx = blockIdx.x * 256 + threadIdx.x;
    const int n = idx & 2047;
    float s = 0.f;
    #pragma unroll
    for (int kc = 0; kc < 8; kc++)
        s += g_part[(size_t)kc * MR * DM + idx];
    out[idx] = s + bo[n];
}

// ---------------------------------------------------------------------------
// Attention: one CTA per (b,h). Flash online softmax over 65 key tiles.
// Staging is XOR-swizzled in 16B chunks so both the K-convert (row read) and
// V-convert (transposed read) are near-conflict-free; all bf16 frag stores
// are packed 32-bit.
// ---------------------------------------------------------------------------
#define KP 136   // pitch for [row][d] arrays -> frag ldu32 conflict-free
#define VP 72    // pitch for [d][key] / [q][key] arrays -> frag ldu32 conflict-free
struct AttnSmem {
    float stK[2][64 * HD];
    float stV[2][64 * HD];
    __nv_bfloat16 Kh[64 * KP], Kl[64 * KP];
    __nv_bfloat16 Vh[HD * VP], Vl[HD * VP];
    __nv_bfloat16 Qh[SNEW * KP], Ql[SNEW * KP];
    float Ss[SNEW * 68];
    __nv_bfloat16 Ph[SNEW * VP], Pl[SNEW * VP];
    float mrow[SNEW], lrow[SNEW], arow[SNEW];
};

// swizzled float offset inside a staged 64x128 tile: chunk = 4 floats
__device__ __forceinline__ int swz(int key, int d) {
    return key * 128 + (((d >> 2) ^ (key & 31)) << 2) + (d & 3);
}

__global__ void __launch_bounds__(256, 1)
attn_kernel(const float* __restrict__ kc, const float* __restrict__ vc) {
    extern __shared__ char smraw[];
    AttnSmem* S = (AttnSmem*)smraw;
    const int bh = blockIdx.x;
    const int tid = threadIdx.x, lane = tid & 31, wid = tid >> 5;

    const float* kbase = kc + (size_t)bh * PAST * HD;
    const float* vbase = vc + (size_t)bh * PAST * HD;
    const float* knew  = g_knew + (size_t)bh * SNEW * HD;
    const float* vnew  = g_vnew + (size_t)bh * SNEW * HD;

    #pragma unroll
    for (int i = 0; i < 8; i++) {
        int idx = i * 256 + tid; int s = idx >> 7, d = idx & 127;
        S->Qh[s * KP + d] = g_qh[(size_t)bh * SNEW * HD + idx];
        S->Ql[s * KP + d] = g_ql[(size_t)bh * SNEW * HD + idx];
    }
    if (tid < SNEW) { S->mrow[tid] = -1e30f; S->lrow[tid] = 0.f; }

    float o[2][4] = {};

    // loader: 16B chunks, XOR-swizzled destination
    auto loadKV = [&](int ti, int buf) {
        const float* kp; const float* vp; int nchunk;
        if (ti < 64) { kp = kbase + (size_t)ti * 64 * HD; vp = vbase + (size_t)ti * 64 * HD; nchunk = 64 * 32; }
        else         { kp = knew; vp = vnew; nchunk = SNEW * 32; }
        #pragma unroll
        for (int i = 0; i < 8; i++) {
            int idx = i * 256 + tid;              // chunk index
            if (idx < nchunk) {
                int key = idx >> 5, dg = idx & 31;
                int dst = key * 128 + ((dg ^ (key & 31)) << 2);
                cp16(&S->stK[buf][dst], kp + key * 128 + dg * 4);
                cp16(&S->stV[buf][dst], vp + key * 128 + dg * 4);
            }
        }
    };

    const int NT = 65;
    loadKV(0, 0);
    cpcommit();

    for (int ti = 0; ti < NT; ti++) {
        int cur = ti & 1;
        if (ti + 1 < NT) { loadKV(ti + 1, cur ^ 1); cpcommit(); cpwait<1>(); }
        else             { cpwait<0>(); }
        __syncthreads();

        const int nk = (ti < 64) ? 64 : SNEW;

        // --- K convert: thread handles (key, d-pair); packed u32 stores ---
        #pragma unroll
        for (int i = 0; i < 16; i++) {
            int idx2 = i * 256 + tid;             // 0..4095
            int key = idx2 >> 6;                  // 0..63
            int d0  = (idx2 & 63) * 2;            // even d
            const float* bp = &S->stK[cur][swz(key, d0)];
            float f0 = (key < nk) ? bp[0] : 0.f;
            float f1 = (key < nk) ? bp[1] : 0.f;
            __nv_bfloat16 h0, l0, h1, l1;
            split2(f0, &h0, &l0); split2(f1, &h1, &l1);
            *reinterpret_cast<uint32_t*>(&S->Kh[key * KP + d0]) = packbf(h0, h1);
            *reinterpret_cast<uint32_t*>(&S->Kl[key * KP + d0]) = packbf(l0, l1);
        }
        // --- V convert (transpose): thread handles (d, key-pair); packed ---
        #pragma unroll
        for (int i = 0; i < 16; i++) {
            int idx2 = i * 256 + tid;             // 0..4095
            int kp2 = (idx2 & 31) * 2;            // even key
            int d   = idx2 >> 5;                  // 0..127
            float f0 = (kp2     < nk) ? S->stV[cur][swz(kp2,     d)] : 0.f;
            float f1 = (kp2 + 1 < nk) ? S->stV[cur][swz(kp2 + 1, d)] : 0.f;
            __nv_bfloat16 h0, l0, h1, l1;
            split2(f0, &h0, &l0); split2(f1, &h1, &l1);
            *reinterpret_cast<uint32_t*>(&S->Vh[d * VP + kp2]) = packbf(h0, h1);
            *reinterpret_cast<uint32_t*>(&S->Vl[d * VP + kp2]) = packbf(l0, l1);
        }
        __syncthreads();

        // --- QK^T: warp w -> score columns [8w, 8w+8), bf16x3 ---
        {
            float sacc[4] = {0.f, 0.f, 0.f, 0.f};
            const int n = wid * 8 + (lane >> 2);
            const int r = lane >> 2, kkb = (lane & 3) * 2;
            #pragma unroll
            for (int ks = 0; ks < 8; ks++) {
                int kk = ks * 16 + kkb;
                uint32_t ah[4], al[4], bh2[2], bl2[2];
                ah[0] = ldu32(&S->Qh[r * KP + kk]);       ah[1] = ldu32(&S->Qh[(r + 8) * KP + kk]);
                ah[2] = ldu32(&S->Qh[r * KP + kk + 8]);   ah[3] = ldu32(&S->Qh[(r + 8) * KP + kk + 8]);
                al[0] = ldu32(&S->Ql[r * KP + kk]);       al[1] = ldu32(&S->Ql[(r + 8) * KP + kk]);
                al[2] = ldu32(&S->Ql[r * KP + kk + 8]);   al[3] = ldu32(&S->Ql[(r + 8) * KP + kk + 8]);
                bh2[0] = ldu32(&S->Kh[n * KP + kk]);      bh2[1] = ldu32(&S->Kh[n * KP + kk + 8]);
                bl2[0] = ldu32(&S->Kl[n * KP + kk]);      bl2[1] = ldu32(&S->Kl[n * KP + kk + 8]);
                mmabf(sacc, ah, bh2);
                mmabf(sacc, ah, bl2);
                mmabf(sacc, al, bh2);
            }
            const int cn = (lane & 3) * 2;
            #pragma unroll
            for (int ci = 0; ci < 4; ci++) {
                int row = r + ((ci & 2) ? 8 : 0);
                int col = wid * 8 + cn + (ci & 1);
                float v = sacc[ci];
                if (ti == 64 && (col > row || col >= SNEW)) v = -1e30f;
                S->Ss[row * 68 + col] = v;
            }
        }
        __syncthreads();

        // --- online softmax: warp w handles rows 2w, 2w+1 ---
        #pragma unroll
        for (int rr = 0; rr < 2; rr++) {
            int row = wid * 2 + rr;
            float s0 = S->Ss[row * 68 + lane];
            float s1 = S->Ss[row * 68 + lane + 32];
            float mx = fmaxf(s0, s1);
            #pragma unroll
            for (int off = 16; off > 0; off >>= 1)
                mx = fmaxf(mx, __shfl_xor_sync(0xffffffffu, mx, off));
            float m_old = S->mrow[row];
            float m_new = fmaxf(m_old, mx);
            float p0 = __expf(s0 - m_new), p1 = __expf(s1 - m_new);
            float ps = p0 + p1;
            #pragma unroll
            for (int off = 16; off > 0; off >>= 1)
                ps += __shfl_xor_sync(0xffffffffu, ps, off);
            if (lane == 0) {
                float alpha = __expf(m_old - m_new);
                S->arow[row] = alpha;
                S->lrow[row] = S->lrow[row] * alpha + ps;
                S->mrow[row] = m_new;
            }
            split2(p0, &S->Ph[row * VP + lane],      &S->Pl[row * VP + lane]);
            split2(p1, &S->Ph[row * VP + lane + 32], &S->Pl[row * VP + lane + 32]);
        }
        __syncthreads();

        // --- rescale O, then PV: warp w -> d columns [16w, 16w+16) ---
        {
            const int r = lane >> 2;
            float a0 = S->arow[r], a1 = S->arow[r + 8];
            #pragma unroll
            for (int ni = 0; ni < 2; ni++) {
                o[ni][0] *= a0; o[ni][1] *= a0;
                o[ni][2] *= a1; o[ni][3] *= a1;
            }
            const int kkb = (lane & 3) * 2;
            #pragma unroll
            for (int ks = 0; ks < 4; ks++) {
                int kk = ks * 16 + kkb;
                uint32_t ah[4], al[4];
                ah[0] = ldu32(&S->Ph[r * VP + kk]);       ah[1] = ldu32(&S->Ph[(r + 8) * VP + kk]);
                ah[2] = ldu32(&S->Ph[r * VP + kk + 8]);   ah[3] = ldu32(&S->Ph[(r + 8) * VP + kk + 8]);
                al[0] = ldu32(&S->Pl[r * VP + kk]);       al[1] = ldu32(&S->Pl[(r + 8) * VP + kk]);
                al[2] = ldu32(&S->Pl[r * VP + kk + 8]);   al[3] = ldu32(&S->Pl[(r + 8) * VP + kk + 8]);
                #pragma unroll
                for (int ni = 0; ni < 2; ni++) {
                    int n = wid * 16 + ni * 8 + r;
                    uint32_t bh2[2], bl2[2];
                    bh2[0] = ldu32(&S->Vh[n * VP + kk]);  bh2[1] = ldu32(&S->Vh[n * VP + kk + 8]);
                    bl2[0] = ldu32(&S->Vl[n * VP + kk]);  bl2[1] = ldu32(&S->Vl[n * VP + kk + 8]);
                    mmabf(o[ni], ah, bh2);
                    mmabf(o[ni], ah, bl2);
                    mmabf(o[ni], al, bh2);
                }
            }
        }
    }
    __syncthreads();

    // epilogue: normalize and write to g_attn [(b*16+q)][h*128+d]
    {
        const int b = bh >> 4, h = bh & 15;
        const int r = lane >> 2, cn = (lane & 3) * 2;
        float li0 = 1.f / S->lrow[r], li1 = 1.f / S->lrow[r + 8];
        #pragma unroll
        for (int ni = 0; ni < 2; ni++) {
            #pragma unroll
            for (int ci = 0; ci < 4; ci++) {
                int row = r + ((ci & 2) ? 8 : 0);
                int col = wid * 16 + ni * 8 + cn + (ci & 1);
                float v = o[ni][ci] * ((ci & 2) ? li1 : li0);
                g_attn[(size_t)(b * SNEW + row) * DM + h * HD + col] = v;
            }
        }
    }
}

// ---------------------------------------------------------------------------
extern "C" void kernel_launch(void* const* d_in, const int* in_sizes, int n_in,
                              void* d_out, int out_size) {
    const float* x  = (const float*)d_in[0];
    const float* kcache = (const float*)d_in[1];
    const float* vcache = (const float*)d_in[2];
    const float* Wq = (const float*)d_in[3];
    const float* bq = (const float*)d_in[4];
    const float* Wk = (const float*)d_in[5];
    const float* bk = (const float*)d_in[6];
    const float* Wv = (const float*)d_in[7];
    const float* bv = (const float*)d_in[8];
    const float* Wo = (const float*)d_in[9];
    const float* bo = (const float*)d_in[10];
    float* out = (float*)d_out;

    cudaFuncSetAttribute(qkv_partial_kernel, cudaFuncAttributeMaxDynamicSharedMemorySize, (int)sizeof(GemmSmem));
    cudaFuncSetAttribute(o_partial_kernel,   cudaFuncAttributeMaxDynamicSharedMemorySize, (int)sizeof(GemmSmem));
    cudaFuncSetAttribute(attn_kernel,        cudaFuncAttributeMaxDynamicSharedMemorySize, (int)sizeof(AttnSmem));

    dim3 gq(32, 8, 3);
    qkv_partial_kernel<<<gq, 256, sizeof(GemmSmem)>>>(x, Wq, Wk, Wv);
    dim3 gr(1024, 3);
    qkv_reduce_kernel<<<gr, 256>>>(bq, bk, bv);
    attn_kernel<<<128, 256, sizeof(AttnSmem)>>>(kcache, vcache);
    dim3 go(32, 8);
    o_partial_kernel<<<go, 256, sizeof(GemmSmem)>>>(Wo);
    o_reduce_kernel<<<1024, 256>>>(bo, out);
}

// round 9
// speedup vs baseline: 1.5954x; 1.1906x over previous
#include <cuda_runtime.h>
#include <cuda_bf16.h>
#include <stdint.h>

#define NB      8
#define SNEW    16
#define DM      2048
#define NH      16
#define HD      128
#define PAST    4096
#define MR      128
#define QSCALE  0.08838834764831843f

// ---------------- device scratch ----------------
__device__ __nv_bfloat16 g_xh[MR * DM], g_xl[MR * DM];          // x split
__device__ __nv_bfloat16 g_wth[4 * DM * DM], g_wtl[4 * DM * DM];// W^T split, [n][k]
__device__ __nv_bfloat16 g_qh[MR * DM], g_ql[MR * DM];          // Q (scaled) split
__device__ float         g_knew[MR * DM], g_vnew[MR * DM];
__device__ __nv_bfloat16 g_oh[MR * DM], g_ol[MR * DM];          // attn out split
__device__ float         g_part[3 * 8 * MR * DM];               // split-K partials

// ---------------- helpers ----------------
__device__ __forceinline__ void cp16(void* s, const void* g) {
    uint32_t sa = (uint32_t)__cvta_generic_to_shared(s);
    asm volatile("cp.async.cg.shared.global [%0], [%1], 16;\n" :: "r"(sa), "l"(g));
}
__device__ __forceinline__ void cpcommit() { asm volatile("cp.async.commit_group;\n"); }
template <int N>
__device__ __forceinline__ void cpwait() { asm volatile("cp.async.wait_group %0;\n" :: "n"(N)); }

__device__ __forceinline__ void mmabf(float* c, const uint32_t* a, const uint32_t* b) {
    asm volatile(
        "mma.sync.aligned.m16n8k16.row.col.f32.bf16.bf16.f32 "
        "{%0,%1,%2,%3},{%4,%5,%6,%7},{%8,%9},{%0,%1,%2,%3};"
        : "+f"(c[0]), "+f"(c[1]), "+f"(c[2]), "+f"(c[3])
        : "r"(a[0]), "r"(a[1]), "r"(a[2]), "r"(a[3]), "r"(b[0]), "r"(b[1]));
}
__device__ __forceinline__ uint32_t ldu32(const __nv_bfloat16* p) {
    return *reinterpret_cast<const uint32_t*>(p);
}
__device__ __forceinline__ void split2(float f, __nv_bfloat16* hp, __nv_bfloat16* lp) {
    __nv_bfloat16 h = __float2bfloat16(f);
    *hp = h;
    *lp = __float2bfloat16(f - __bfloat162float(h));
}
// rn split of a pair -> packed u32 hi, packed u32 lo
__device__ __forceinline__ void split_pack_rn(float f0, float f1, uint32_t* hp, uint32_t* lp) {
    __nv_bfloat16 h0, l0, h1, l1;
    split2(f0, &h0, &l0); split2(f1, &h1, &l1);
    uint16_t a0 = *reinterpret_cast<uint16_t*>(&h0), a1 = *reinterpret_cast<uint16_t*>(&h1);
    uint16_t b0 = *reinterpret_cast<uint16_t*>(&l0), b1 = *reinterpret_cast<uint16_t*>(&l1);
    *hp = (uint32_t)a0 | ((uint32_t)a1 << 16);
    *lp = (uint32_t)b0 | ((uint32_t)b1 << 16);
}
// rz (truncate) split of a pair: hi via PRMT, lo via cvt.bf16x2
__device__ __forceinline__ void split_pack_rz(float f0, float f1, uint32_t* hp, uint32_t* lp) {
    uint32_t b0 = __float_as_uint(f0), b1 = __float_as_uint(f1);
    *hp = __byte_perm(b0, b1, 0x7632);
    float lo0 = f0 - __uint_as_float(b0 & 0xFFFF0000u);
    float lo1 = f1 - __uint_as_float(b1 & 0xFFFF0000u);
    uint32_t lp2;
    asm("cvt.rn.bf16x2.f32 %0, %1, %2;" : "=r"(lp2) : "f"(lo1), "f"(lo0));
    *lp = lp2;
}

// ---------------------------------------------------------------------------
// Prep: W[k][n] fp32 -> Wt[n][k] bf16 hi/lo (tiled transpose); x -> hi/lo
// ---------------------------------------------------------------------------
__global__ void __launch_bounds__(256)
prep_w_kernel(const float* __restrict__ Wq, const float* __restrict__ Wk,
              const float* __restrict__ Wv, const float* __restrict__ Wo) {
    __shared__ float st[64 * 68];
    const int z = blockIdx.z;
    const float* W = (z == 0) ? Wq : ((z == 1) ? Wk : ((z == 2) ? Wv : Wo));
    const int k0 = blockIdx.y * 64, n0 = blockIdx.x * 64;
    const int tid = threadIdx.x;

    #pragma unroll
    for (int it = 0; it < 4; it++) {
        int i = (tid >> 4) + it * 16, j4 = (tid & 15) * 4;
        float4 v = *reinterpret_cast<const float4*>(&W[(size_t)(k0 + i) * DM + n0 + j4]);
        st[i * 68 + j4 + 0] = v.x; st[i * 68 + j4 + 1] = v.y;
        st[i * 68 + j4 + 2] = v.z; st[i * 68 + j4 + 3] = v.w;
    }
    __syncthreads();

    const int j = tid >> 2;
    __nv_bfloat16* wh = g_wth + (size_t)z * DM * DM;
    __nv_bfloat16* wl = g_wtl + (size_t)z * DM * DM;
    #pragma unroll
    for (int it = 0; it < 8; it++) {
        int kk2 = (tid & 3) + it * 4;       // u32 index 0..31
        int i = kk2 * 2;
        float f0 = st[i * 68 + j], f1 = st[(i + 1) * 68 + j];
        uint32_t hp, lp;
        split_pack_rn(f0, f1, &hp, &lp);
        size_t o = (size_t)(n0 + j) * DM + k0 + i;
        *reinterpret_cast<uint32_t*>(&wh[o]) = hp;
        *reinterpret_cast<uint32_t*>(&wl[o]) = lp;
    }
}

__global__ void __launch_bounds__(256)
prep_x_kernel(const float* __restrict__ x) {
    int idx2 = (blockIdx.x * 256 + threadIdx.x) * 2;
    float2 f = *reinterpret_cast<const float2*>(&x[idx2]);
    uint32_t hp, lp;
    split_pack_rn(f.x, f.y, &hp, &lp);
    *reinterpret_cast<uint32_t*>(&g_xh[idx2]) = hp;
    *reinterpret_cast<uint32_t*>(&g_xl[idx2]) = lp;
}

// ---------------------------------------------------------------------------
// Split-K GEMM partial, pure bf16 path. BK=64, 4 iters/CTA, 2 CTAs/SM.
// Pitch 72 bf16 (=36 words, 36 % 8 == 4) -> all frag ldu32 conflict-free.
// ---------------------------------------------------------------------------
#define AP 72
struct GemmSmem {
    __nv_bfloat16 Ah[2][MR * AP], Al[2][MR * AP];
    __nv_bfloat16 Bh[2][64 * AP], Bl[2][64 * AP];
};

__device__ __forceinline__ void gemm_stage(GemmSmem* S, int st,
                                           const __nv_bfloat16* Ahp, const __nv_bfloat16* Alp,
                                           const __nv_bfloat16* Bhp, const __nv_bfloat16* Blp,
                                           int nb, int kbase) {
    const int tid = threadIdx.x;
    #pragma unroll
    for (int i = 0; i < 4; i++) {
        int idx = tid + i * 256; int r = idx >> 3, c = (idx & 7) * 8;
        cp16(&S->Ah[st][r * AP + c], Ahp + (size_t)r * DM + kbase + c);
        cp16(&S->Al[st][r * AP + c], Alp + (size_t)r * DM + kbase + c);
    }
    #pragma unroll
    for (int i = 0; i < 2; i++) {
        int idx = tid + i * 256; int n = idx >> 3, c = (idx & 7) * 8;
        cp16(&S->Bh[st][n * AP + c], Bhp + (size_t)(nb * 64 + n) * DM + kbase + c);
        cp16(&S->Bl[st][n * AP + c], Blp + (size_t)(nb * 64 + n) * DM + kbase + c);
    }
}

__device__ __forceinline__ void gemm_core(const __nv_bfloat16* Ahp, const __nv_bfloat16* Alp,
                                          const __nv_bfloat16* Bhp, const __nv_bfloat16* Blp,
                                          GemmSmem* S, float acc[2][4][4], int nb, int k0) {
    const int tid = threadIdx.x, lane = tid & 31;
    const int warpM = (tid >> 5) & 3, warpN = tid >> 7;

    gemm_stage(S, 0, Ahp, Alp, Bhp, Blp, nb, k0);
    cpcommit();

    #pragma unroll 1
    for (int kt = 0; kt < 4; kt++) {
        int cur = kt & 1;
        if (kt < 3) {
            gemm_stage(S, cur ^ 1, Ahp, Alp, Bhp, Blp, nb, k0 + (kt + 1) * 64);
            cpcommit();
            cpwait<1>();
        } else {
            cpwait<0>();
        }
        __syncthreads();

        #pragma unroll
        for (int ks = 0; ks < 4; ks++) {
            const int kk = ks * 16 + (lane & 3) * 2, r0 = lane >> 2;
            uint32_t ah[2][4], al[2][4];
            #pragma unroll
            for (int mi = 0; mi < 2; mi++) {
                int r = warpM * 32 + mi * 16 + r0;
                ah[mi][0] = ldu32(&S->Ah[cur][r * AP + kk]);
                ah[mi][1] = ldu32(&S->Ah[cur][(r + 8) * AP + kk]);
                ah[mi][2] = ldu32(&S->Ah[cur][r * AP + kk + 8]);
                ah[mi][3] = ldu32(&S->Ah[cur][(r + 8) * AP + kk + 8]);
                al[mi][0] = ldu32(&S->Al[cur][r * AP + kk]);
                al[mi][1] = ldu32(&S->Al[cur][(r + 8) * AP + kk]);
                al[mi][2] = ldu32(&S->Al[cur][r * AP + kk + 8]);
                al[mi][3] = ldu32(&S->Al[cur][(r + 8) * AP + kk + 8]);
            }
            #pragma unroll
            for (int ni = 0; ni < 4; ni++) {
                int n = warpN * 32 + ni * 8 + r0;
                uint32_t bh[2], bl[2];
                bh[0] = ldu32(&S->Bh[cur][n * AP + kk]); bh[1] = ldu32(&S->Bh[cur][n * AP + kk + 8]);
                bl[0] = ldu32(&S->Bl[cur][n * AP + kk]); bl[1] = ldu32(&S->Bl[cur][n * AP + kk + 8]);
                #pragma unroll
                for (int mi = 0; mi < 2; mi++) {
                    mmabf(acc[mi][ni], ah[mi], bh);
                    mmabf(acc[mi][ni], ah[mi], bl);
                    mmabf(acc[mi][ni], al[mi], bh);
                }
            }
        }
        __syncthreads();
    }
}

__device__ __forceinline__ void store_partial(float acc[2][4][4], float* dst, int nb) {
    const int lane = threadIdx.x & 31, warpM = (threadIdx.x >> 5) & 3, warpN = threadIdx.x >> 7;
    #pragma unroll
    for (int mi = 0; mi < 2; mi++) {
        #pragma unroll
        for (int ni = 0; ni < 4; ni++) {
            int rb = warpM * 32 + mi * 16 + (lane >> 2);
            int cb = nb * 64 + warpN * 32 + ni * 8 + (lane & 3) * 2;
            #pragma unroll
            for (int ci = 0; ci < 4; ci++) {
                int m = rb + ((ci & 2) ? 8 : 0);
                int n = cb + (ci & 1);
                dst[(size_t)m * DM + n] = acc[mi][ni][ci];
            }
        }
    }
}

__global__ void __launch_bounds__(256, 2)
qkv_partial_kernel() {
    extern __shared__ char smraw[];
    GemmSmem* S = (GemmSmem*)smraw;
    const int nb = blockIdx.x, kc = blockIdx.y, z = blockIdx.z;
    const __nv_bfloat16* wh = g_wth + (size_t)z * DM * DM;
    const __nv_bfloat16* wl = g_wtl + (size_t)z * DM * DM;
    float acc[2][4][4] = {};
    gemm_core(g_xh, g_xl, wh, wl, S, acc, nb, kc * 256);
    store_partial(acc, g_part + (size_t)(z * 8 + kc) * MR * DM, nb);
}

__global__ void __launch_bounds__(256)
qkv_reduce_kernel(const float* __restrict__ bq, const float* __restrict__ bk,
                  const float* __restrict__ bv) {
    const int z = blockIdx.y;
    const int idx2 = (blockIdx.x * 256 + threadIdx.x) * 2;
    const int m = idx2 >> 11, n = idx2 & 2047;
    float s0 = 0.f, s1 = 0.f;
    #pragma unroll
    for (int kc = 0; kc < 8; kc++) {
        float2 p = *reinterpret_cast<const float2*>(&g_part[(size_t)(z * 8 + kc) * MR * DM + idx2]);
        s0 += p.x; s1 += p.y;
    }
    const int qidx = (((m >> 4) * NH + (n >> 7)) * SNEW + (m & 15)) * HD + (n & 127);
    if (z == 0) {
        s0 = (s0 + bq[n]) * QSCALE;
        s1 = (s1 + bq[n + 1]) * QSCALE;
        uint32_t hp, lp;
        split_pack_rn(s0, s1, &hp, &lp);
        *reinterpret_cast<uint32_t*>(&g_qh[qidx]) = hp;
        *reinterpret_cast<uint32_t*>(&g_ql[qidx]) = lp;
    } else if (z == 1) {
        float2 r; r.x = s0 + bk[n]; r.y = s1 + bk[n + 1];
        *reinterpret_cast<float2*>(&g_knew[qidx]) = r;
    } else {
        float2 r; r.x = s0 + bv[n]; r.y = s1 + bv[n + 1];
        *reinterpret_cast<float2*>(&g_vnew[qidx]) = r;
    }
}

__global__ void __launch_bounds__(256, 2)
o_partial_kernel() {
    extern __shared__ char smraw[];
    GemmSmem* S = (GemmSmem*)smraw;
    const int nb = blockIdx.x, kc = blockIdx.y;
    const __nv_bfloat16* wh = g_wth + (size_t)3 * DM * DM;
    const __nv_bfloat16* wl = g_wtl + (size_t)3 * DM * DM;
    float acc[2][4][4] = {};
    gemm_core(g_oh, g_ol, wh, wl, S, acc, nb, kc * 256);
    store_partial(acc, g_part + (size_t)kc * MR * DM, nb);
}

__global__ void __launch_bounds__(256)
o_reduce_kernel(const float* __restrict__ bo, float* __restrict__ out) {
    const int idx = blockIdx.x * 256 + threadIdx.x;
    const int n = idx & 2047;
    float s = 0.f;
    #pragma unroll
    for (int kc = 0; kc < 8; kc++)
        s += g_part[(size_t)kc * MR * DM + idx];
    out[idx] = s + bo[n];
}

// ---------------------------------------------------------------------------
// Attention: one CTA per (b,h). Flash online softmax over 65 key tiles.
// ---------------------------------------------------------------------------
#define KP 136
#define VP 72
struct AttnSmem {
    float stK[2][64 * HD];
    float stV[2][64 * HD];
    __nv_bfloat16 Kh[64 * KP], Kl[64 * KP];
    __nv_bfloat16 Vh[HD * VP], Vl[HD * VP];
    float Ss[SNEW * 68];
    __nv_bfloat16 Ph[SNEW * VP], Pl[SNEW * VP];
    float mrow[SNEW], lrow[SNEW], arow[SNEW];
};

__device__ __forceinline__ int swz(int key, int d) {
    return key * 128 + (((d >> 2) ^ (key & 31)) << 2) + (d & 3);
}

__global__ void __launch_bounds__(256, 1)
attn_kernel(const float* __restrict__ kc, const float* __restrict__ vc) {
    extern __shared__ char smraw[];
    AttnSmem* S = (AttnSmem*)smraw;
    const int bh = blockIdx.x;
    const int tid = threadIdx.x, lane = tid & 31, wid = tid >> 5;

    const float* kbase = kc + (size_t)bh * PAST * HD;
    const float* vbase = vc + (size_t)bh * PAST * HD;
    const float* knew  = g_knew + (size_t)bh * SNEW * HD;
    const float* vnew  = g_vnew + (size_t)bh * SNEW * HD;

    if (tid < SNEW) { S->mrow[tid] = -1e30f; S->lrow[tid] = 0.f; }

    // hoist Q fragments into registers (loop-invariant across tiles)
    uint32_t qfh[8][4], qfl[8][4];
    {
        const __nv_bfloat16* qhp = g_qh + (size_t)bh * SNEW * HD;
        const __nv_bfloat16* qlp = g_ql + (size_t)bh * SNEW * HD;
        const int r = lane >> 2;
        #pragma unroll
        for (int ks = 0; ks < 8; ks++) {
            int kk = ks * 16 + (lane & 3) * 2;
            qfh[ks][0] = ldu32(&qhp[r * HD + kk]);
            qfh[ks][1] = ldu32(&qhp[(r + 8) * HD + kk]);
            qfh[ks][2] = ldu32(&qhp[r * HD + kk + 8]);
            qfh[ks][3] = ldu32(&qhp[(r + 8) * HD + kk + 8]);
            qfl[ks][0] = ldu32(&qlp[r * HD + kk]);
            qfl[ks][1] = ldu32(&qlp[(r + 8) * HD + kk]);
            qfl[ks][2] = ldu32(&qlp[r * HD + kk + 8]);
            qfl[ks][3] = ldu32(&qlp[(r + 8) * HD + kk + 8]);
        }
    }

    float o[2][4] = {};

    auto loadKV = [&](int ti, int buf) {
        const float* kp; const float* vp; int nchunk;
        if (ti < 64) { kp = kbase + (size_t)ti * 64 * HD; vp = vbase + (size_t)ti * 64 * HD; nchunk = 64 * 32; }
        else         { kp = knew; vp = vnew; nchunk = SNEW * 32; }
        #pragma unroll
        for (int i = 0; i < 8; i++) {
            int idx = i * 256 + tid;
            if (idx < nchunk) {
                int key = idx >> 5, dg = idx & 31;
                int dst = key * 128 + ((dg ^ (key & 31)) << 2);
                cp16(&S->stK[buf][dst], kp + key * 128 + dg * 4);
                cp16(&S->stV[buf][dst], vp + key * 128 + dg * 4);
            }
        }
    };

    const int NT = 65;
    loadKV(0, 0);
    cpcommit();

    for (int ti = 0; ti < NT; ti++) {
        int cur = ti & 1;
        if (ti + 1 < NT) { loadKV(ti + 1, cur ^ 1); cpcommit(); cpwait<1>(); }
        else             { cpwait<0>(); }
        __syncthreads();

        const int nk = (ti < 64) ? 64 : SNEW;

        // K convert: (key, d-pair), rz split, packed stores
        #pragma unroll
        for (int i = 0; i < 16; i++) {
            int idx2 = i * 256 + tid;
            int key = idx2 >> 6, d0 = (idx2 & 63) * 2;
            float2 f = *reinterpret_cast<const float2*>(&S->stK[cur][swz(key, d0)]);
            if (key >= nk) { f.x = 0.f; f.y = 0.f; }
            uint32_t hp, lp;
            split_pack_rz(f.x, f.y, &hp, &lp);
            *reinterpret_cast<uint32_t*>(&S->Kh[key * KP + d0]) = hp;
            *reinterpret_cast<uint32_t*>(&S->Kl[key * KP + d0]) = lp;
        }
        // V convert (transpose): (d, key-pair)
        #pragma unroll
        for (int i = 0; i < 16; i++) {
            int idx2 = i * 256 + tid;
            int kp2 = (idx2 & 31) * 2, d = idx2 >> 5;
            float f0 = (kp2 < nk) ? S->stV[cur][swz(kp2, d)]     : 0.f;
            float f1 = (kp2 < nk) ? S->stV[cur][swz(kp2 + 1, d)] : 0.f;
            uint32_t hp, lp;
            split_pack_rz(f0, f1, &hp, &lp);
            *reinterpret_cast<uint32_t*>(&S->Vh[d * VP + kp2]) = hp;
            *reinterpret_cast<uint32_t*>(&S->Vl[d * VP + kp2]) = lp;
        }
        __syncthreads();

        // QK^T: warp w -> score columns [8w, 8w+8)
        {
            float sacc[4] = {0.f, 0.f, 0.f, 0.f};
            const int n = wid * 8 + (lane >> 2);
            const int r = lane >> 2;
            #pragma unroll
            for (int ks = 0; ks < 8; ks++) {
                int kk = ks * 16 + (lane & 3) * 2;
                uint32_t bh2[2], bl2[2];
                bh2[0] = ldu32(&S->Kh[n * KP + kk]); bh2[1] = ldu32(&S->Kh[n * KP + kk + 8]);
                bl2[0] = ldu32(&S->Kl[n * KP + kk]); bl2[1] = ldu32(&S->Kl[n * KP + kk + 8]);
                mmabf(sacc, qfh[ks], bh2);
                mmabf(sacc, qfh[ks], bl2);
                mmabf(sacc, qfl[ks], bh2);
            }
            const int cn = (lane & 3) * 2;
            #pragma unroll
            for (int ci = 0; ci < 4; ci++) {
                int row = r + ((ci & 2) ? 8 : 0);
                int col = wid * 8 + cn + (ci & 1);
                float v = sacc[ci];
                if (ti == 64 && (col > row || col >= SNEW)) v = -1e30f;
                S->Ss[row * 68 + col] = v;
            }
        }
        __syncthreads();

        // online softmax: one row per half-warp (16 rows in parallel)
        {
            const int half = lane >> 4, l4 = lane & 15;
            const int row = wid * 2 + half;
            float4 sv = *reinterpret_cast<const float4*>(&S->Ss[row * 68 + l4 * 4]);
            float mx = fmaxf(fmaxf(sv.x, sv.y), fmaxf(sv.z, sv.w));
            #pragma unroll
            for (int off = 8; off > 0; off >>= 1)
                mx = fmaxf(mx, __shfl_xor_sync(0xffffffffu, mx, off));
            float m_old = S->mrow[row];
            float m_new = fmaxf(m_old, mx);
            float p0 = __expf(sv.x - m_new), p1 = __expf(sv.y - m_new);
            float p2 = __expf(sv.z - m_new), p3 = __expf(sv.w - m_new);
            float ps = (p0 + p1) + (p2 + p3);
            #pragma unroll
            for (int off = 8; off > 0; off >>= 1)
                ps += __shfl_xor_sync(0xffffffffu, ps, off);
            if (l4 == 0) {
                float alpha = __expf(m_old - m_new);
                S->arow[row] = alpha;
                S->lrow[row] = S->lrow[row] * alpha + ps;
                S->mrow[row] = m_new;
            }
            uint32_t hp, lp;
            split_pack_rz(p0, p1, &hp, &lp);
            *reinterpret_cast<uint32_t*>(&S->Ph[row * VP + l4 * 4]) = hp;
            *reinterpret_cast<uint32_t*>(&S->Pl[row * VP + l4 * 4]) = lp;
            split_pack_rz(p2, p3, &hp, &lp);
            *reinterpret_cast<uint32_t*>(&S->Ph[row * VP + l4 * 4 + 2]) = hp;
            *reinterpret_cast<uint32_t*>(&S->Pl[row * VP + l4 * 4 + 2]) = lp;
        }
        __syncthreads();

        // rescale O, then PV: warp w -> d columns [16w, 16w+16)
        {
            const int r = lane >> 2;
            float a0 = S->arow[r], a1 = S->arow[r + 8];
            #pragma unroll
            for (int ni = 0; ni < 2; ni++) {
                o[ni][0] *= a0; o[ni][1] *= a0;
                o[ni][2] *= a1; o[ni][3] *= a1;
            }
            #pragma unroll
            for (int ks = 0; ks < 4; ks++) {
                int kk = ks * 16 + (lane & 3) * 2;
                uint32_t ah[4], al[4];
                ah[0] = ldu32(&S->Ph[r * VP + kk]);       ah[1] = ldu32(&S->Ph[(r + 8) * VP + kk]);
                ah[2] = ldu32(&S->Ph[r * VP + kk + 8]);   ah[3] = ldu32(&S->Ph[(r + 8) * VP + kk + 8]);
                al[0] = ldu32(&S->Pl[r * VP + kk]);       al[1] = ldu32(&S->Pl[(r + 8) * VP + kk]);
                al[2] = ldu32(&S->Pl[r * VP + kk + 8]);   al[3] = ldu32(&S->Pl[(r + 8) * VP + kk + 8]);
                #pragma unroll
                for (int ni = 0; ni < 2; ni++) {
                    int n = wid * 16 + ni * 8 + r;
                    uint32_t bh2[2], bl2[2];
                    bh2[0] = ldu32(&S->Vh[n * VP + kk]);  bh2[1] = ldu32(&S->Vh[n * VP + kk + 8]);
                    bl2[0] = ldu32(&S->Vl[n * VP + kk]);  bl2[1] = ldu32(&S->Vl[n * VP + kk + 8]);
                    mmabf(o[ni], ah, bh2);
                    mmabf(o[ni], ah, bl2);
                    mmabf(o[ni], al, bh2);
                }
            }
        }
    }
    __syncthreads();

    // epilogue: normalize, split to bf16 hi/lo, write g_oh/g_ol
    {
        const int b = bh >> 4, h = bh & 15;
        const int r = lane >> 2, cn = (lane & 3) * 2;
        float li0 = 1.f / S->lrow[r], li1 = 1.f / S->lrow[r + 8];
        #pragma unroll
        for (int ni = 0; ni < 2; ni++) {
            #pragma unroll
            for (int p2 = 0; p2 < 2; p2++) {           // ci pair: (0,1) row r; (2,3) row r+8
                int row = r + (p2 ? 8 : 0);
                float li = p2 ? li1 : li0;
                float v0 = o[ni][p2 * 2 + 0] * li;
                float v1 = o[ni][p2 * 2 + 1] * li;
                int col = wid * 16 + ni * 8 + cn;
                size_t oidx = (size_t)(b * SNEW + row) * DM + h * HD + col;
                uint32_t hp, lp;
                split_pack_rn(v0, v1, &hp, &lp);
                *reinterpret_cast<uint32_t*>(&g_oh[oidx]) = hp;
                *reinterpret_cast<uint32_t*>(&g_ol[oidx]) = lp;
            }
        }
    }
}

// ---------------------------------------------------------------------------
extern "C" void kernel_launch(void* const* d_in, const int* in_sizes, int n_in,
                              void* d_out, int out_size) {
    const float* x      = (const float*)d_in[0];
    const float* kcache = (const float*)d_in[1];
    const float* vcache = (const float*)d_in[2];
    const float* Wq = (const float*)d_in[3];
    const float* bq = (const float*)d_in[4];
    const float* Wk = (const float*)d_in[5];
    const float* bk = (const float*)d_in[6];
    const float* Wv = (const float*)d_in[7];
    const float* bv = (const float*)d_in[8];
    const float* Wo = (const float*)d_in[9];
    const float* bo = (const float*)d_in[10];
    float* out = (float*)d_out;

    cudaFuncSetAttribute(qkv_partial_kernel, cudaFuncAttributeMaxDynamicSharedMemorySize, (int)sizeof(GemmSmem));
    cudaFuncSetAttribute(o_partial_kernel,   cudaFuncAttributeMaxDynamicSharedMemorySize, (int)sizeof(GemmSmem));
    cudaFuncSetAttribute(attn_kernel,        cudaFuncAttributeMaxDynamicSharedMemorySize, (int)sizeof(AttnSmem));

    dim3 gw(32, 32, 4);
    prep_w_kernel<<<gw, 256>>>(Wq, Wk, Wv, Wo);
    prep_x_kernel<<<512, 256>>>(x);
    dim3 gq(32, 8, 3);
    qkv_partial_kernel<<<gq, 256, sizeof(GemmSmem)>>>();
    dim3 gr(512, 3);
    qkv_reduce_kernel<<<gr, 256>>>(bq, bk, bv);
    attn_kernel<<<128, 256, sizeof(AttnSmem)>>>(kcache, vcache);
    dim3 go(32, 8);
    o_partial_kernel<<<go, 256, sizeof(GemmSmem)>>>();
    o_reduce_kernel<<<1024, 256>>>(bo, out);
}

// round 13
// speedup vs baseline: 2.0719x; 1.2987x over previous
#include <cuda_runtime.h>
#include <cuda_bf16.h>
#include <stdint.h>

#define NB      8
#define SNEW    16
#define DM      2048
#define NH      16
#define HD      128
#define PAST    4096
#define MR      128
#define QSCALE  0.08838834764831843f

// ---------------- device scratch ----------------
__device__ __nv_bfloat16 g_xh[MR * DM], g_xl[MR * DM];          // x split
__device__ __nv_bfloat16 g_wth[4 * DM * DM], g_wtl[4 * DM * DM];// W^T split, [n][k]
__device__ __nv_bfloat16 g_qh[MR * DM], g_ql[MR * DM];          // Q (scaled) split
__device__ float         g_knew[MR * DM], g_vnew[MR * DM];
__device__ __nv_bfloat16 g_oh[MR * DM], g_ol[MR * DM];          // attn out split
__device__ float         g_part[3 * 8 * MR * DM];               // split-K partials

// ---------------- helpers ----------------
__device__ __forceinline__ void cp16(void* s, const void* g) {
    uint32_t sa = (uint32_t)__cvta_generic_to_shared(s);
    asm volatile("cp.async.cg.shared.global [%0], [%1], 16;\n" :: "r"(sa), "l"(g));
}
__device__ __forceinline__ void cpcommit() { asm volatile("cp.async.commit_group;\n"); }
template <int N>
__device__ __forceinline__ void cpwait() { asm volatile("cp.async.wait_group %0;\n" :: "n"(N)); }

__device__ __forceinline__ void mmabf(float* c, const uint32_t* a, const uint32_t* b) {
    asm volatile(
        "mma.sync.aligned.m16n8k16.row.col.f32.bf16.bf16.f32 "
        "{%0,%1,%2,%3},{%4,%5,%6,%7},{%8,%9},{%0,%1,%2,%3};"
        : "+f"(c[0]), "+f"(c[1]), "+f"(c[2]), "+f"(c[3])
        : "r"(a[0]), "r"(a[1]), "r"(a[2]), "r"(a[3]), "r"(b[0]), "r"(b[1]));
}
__device__ __forceinline__ uint32_t ldu32(const __nv_bfloat16* p) {
    return *reinterpret_cast<const uint32_t*>(p);
}
__device__ __forceinline__ void split2(float f, __nv_bfloat16* hp, __nv_bfloat16* lp) {
    __nv_bfloat16 h = __float2bfloat16(f);
    *hp = h;
    *lp = __float2bfloat16(f - __bfloat162float(h));
}
// rn split of a pair -> packed u32 hi, packed u32 lo
__device__ __forceinline__ void split_pack_rn(float f0, float f1, uint32_t* hp, uint32_t* lp) {
    __nv_bfloat16 h0, l0, h1, l1;
    split2(f0, &h0, &l0); split2(f1, &h1, &l1);
    uint16_t a0 = *reinterpret_cast<uint16_t*>(&h0), a1 = *reinterpret_cast<uint16_t*>(&h1);
    uint16_t b0 = *reinterpret_cast<uint16_t*>(&l0), b1 = *reinterpret_cast<uint16_t*>(&l1);
    *hp = (uint32_t)a0 | ((uint32_t)a1 << 16);
    *lp = (uint32_t)b0 | ((uint32_t)b1 << 16);
}
// rz (truncate) split of a pair: hi via PRMT, lo via cvt.bf16x2
__device__ __forceinline__ void split_pack_rz(float f0, float f1, uint32_t* hp, uint32_t* lp) {
    uint32_t b0 = __float_as_uint(f0), b1 = __float_as_uint(f1);
    *hp = __byte_perm(b0, b1, 0x7632);
    float lo0 = f0 - __uint_as_float(b0 & 0xFFFF0000u);
    float lo1 = f1 - __uint_as_float(b1 & 0xFFFF0000u);
    uint32_t lp2;
    asm("cvt.rn.bf16x2.f32 %0, %1, %2;" : "=r"(lp2) : "f"(lo1), "f"(lo0));
    *lp = lp2;
}

// ---------------------------------------------------------------------------
// Prep: W[k][n] fp32 -> Wt[n][k] bf16 hi/lo (tiled transpose); x -> hi/lo
// ---------------------------------------------------------------------------
__global__ void __launch_bounds__(256)
prep_w_kernel(const float* __restrict__ Wq, const float* __restrict__ Wk,
              const float* __restrict__ Wv, const float* __restrict__ Wo) {
    __shared__ float st[64 * 68];
    const int z = blockIdx.z;
    const float* W = (z == 0) ? Wq : ((z == 1) ? Wk : ((z == 2) ? Wv : Wo));
    const int k0 = blockIdx.y * 64, n0 = blockIdx.x * 64;
    const int tid = threadIdx.x;

    #pragma unroll
    for (int it = 0; it < 4; it++) {
        int i = (tid >> 4) + it * 16, j4 = (tid & 15) * 4;
        float4 v = *reinterpret_cast<const float4*>(&W[(size_t)(k0 + i) * DM + n0 + j4]);
        st[i * 68 + j4 + 0] = v.x; st[i * 68 + j4 + 1] = v.y;
        st[i * 68 + j4 + 2] = v.z; st[i * 68 + j4 + 3] = v.w;
    }
    __syncthreads();

    const int j = tid >> 2;
    __nv_bfloat16* wh = g_wth + (size_t)z * DM * DM;
    __nv_bfloat16* wl = g_wtl + (size_t)z * DM * DM;
    #pragma unroll
    for (int it = 0; it < 8; it++) {
        int kk2 = (tid & 3) + it * 4;       // u32 index 0..31
        int i = kk2 * 2;
        float f0 = st[i * 68 + j], f1 = st[(i + 1) * 68 + j];
        uint32_t hp, lp;
        split_pack_rn(f0, f1, &hp, &lp);
        size_t o = (size_t)(n0 + j) * DM + k0 + i;
        *reinterpret_cast<uint32_t*>(&wh[o]) = hp;
        *reinterpret_cast<uint32_t*>(&wl[o]) = lp;
    }
}

__global__ void __launch_bounds__(256)
prep_x_kernel(const float* __restrict__ x) {
    int idx2 = (blockIdx.x * 256 + threadIdx.x) * 2;
    float2 f = *reinterpret_cast<const float2*>(&x[idx2]);
    uint32_t hp, lp;
    split_pack_rn(f.x, f.y, &hp, &lp);
    *reinterpret_cast<uint32_t*>(&g_xh[idx2]) = hp;
    *reinterpret_cast<uint32_t*>(&g_xl[idx2]) = lp;
}

// ---------------------------------------------------------------------------
// Split-K GEMM partial, pure bf16 path. BK=64, 4 iters/CTA, 2 CTAs/SM.
// Pitch 72 bf16 (=36 words, 36 % 8 == 4) -> all frag ldu32 conflict-free.
// ---------------------------------------------------------------------------
#define AP 72
struct GemmSmem {
    __nv_bfloat16 Ah[2][MR * AP], Al[2][MR * AP];
    __nv_bfloat16 Bh[2][64 * AP], Bl[2][64 * AP];
};

__device__ __forceinline__ void gemm_stage(GemmSmem* S, int st,
                                           const __nv_bfloat16* Ahp, const __nv_bfloat16* Alp,
                                           const __nv_bfloat16* Bhp, const __nv_bfloat16* Blp,
                                           int nb, int kbase) {
    const int tid = threadIdx.x;
    #pragma unroll
    for (int i = 0; i < 4; i++) {
        int idx = tid + i * 256; int r = idx >> 3, c = (idx & 7) * 8;
        cp16(&S->Ah[st][r * AP + c], Ahp + (size_t)r * DM + kbase + c);
        cp16(&S->Al[st][r * AP + c], Alp + (size_t)r * DM + kbase + c);
    }
    #pragma unroll
    for (int i = 0; i < 2; i++) {
        int idx = tid + i * 256; int n = idx >> 3, c = (idx & 7) * 8;
        cp16(&S->Bh[st][n * AP + c], Bhp + (size_t)(nb * 64 + n) * DM + kbase + c);
        cp16(&S->Bl[st][n * AP + c], Blp + (size_t)(nb * 64 + n) * DM + kbase + c);
    }
}

__device__ __forceinline__ void gemm_core(const __nv_bfloat16* Ahp, const __nv_bfloat16* Alp,
                                          const __nv_bfloat16* Bhp, const __nv_bfloat16* Blp,
                                          GemmSmem* S, float acc[2][4][4], int nb, int k0) {
    const int tid = threadIdx.x, lane = tid & 31;
    const int warpM = (tid >> 5) & 3, warpN = tid >> 7;

    gemm_stage(S, 0, Ahp, Alp, Bhp, Blp, nb, k0);
    cpcommit();

    #pragma unroll 1
    for (int kt = 0; kt < 4; kt++) {
        int cur = kt & 1;
        if (kt < 3) {
            gemm_stage(S, cur ^ 1, Ahp, Alp, Bhp, Blp, nb, k0 + (kt + 1) * 64);
            cpcommit();
            cpwait<1>();
        } else {
            cpwait<0>();
        }
        __syncthreads();

        #pragma unroll
        for (int ks = 0; ks < 4; ks++) {
            const int kk = ks * 16 + (lane & 3) * 2, r0 = lane >> 2;
            uint32_t ah[2][4], al[2][4];
            #pragma unroll
            for (int mi = 0; mi < 2; mi++) {
                int r = warpM * 32 + mi * 16 + r0;
                ah[mi][0] = ldu32(&S->Ah[cur][r * AP + kk]);
                ah[mi][1] = ldu32(&S->Ah[cur][(r + 8) * AP + kk]);
                ah[mi][2] = ldu32(&S->Ah[cur][r * AP + kk + 8]);
                ah[mi][3] = ldu32(&S->Ah[cur][(r + 8) * AP + kk + 8]);
                al[mi][0] = ldu32(&S->Al[cur][r * AP + kk]);
                al[mi][1] = ldu32(&S->Al[cur][(r + 8) * AP + kk]);
                al[mi][2] = ldu32(&S->Al[cur][r * AP + kk + 8]);
                al[mi][3] = ldu32(&S->Al[cur][(r + 8) * AP + kk + 8]);
            }
            #pragma unroll
            for (int ni = 0; ni < 4; ni++) {
                int n = warpN * 32 + ni * 8 + r0;
                uint32_t bh[2], bl[2];
                bh[0] = ldu32(&S->Bh[cur][n * AP + kk]); bh[1] = ldu32(&S->Bh[cur][n * AP + kk + 8]);
                bl[0] = ldu32(&S->Bl[cur][n * AP + kk]); bl[1] = ldu32(&S->Bl[cur][n * AP + kk + 8]);
                #pragma unroll
                for (int mi = 0; mi < 2; mi++) {
                    mmabf(acc[mi][ni], ah[mi], bh);
                    mmabf(acc[mi][ni], ah[mi], bl);
                    mmabf(acc[mi][ni], al[mi], bh);
                }
            }
        }
        __syncthreads();
    }
}

__device__ __forceinline__ void store_partial(float acc[2][4][4], float* dst, int nb) {
    const int lane = threadIdx.x & 31, warpM = (threadIdx.x >> 5) & 3, warpN = threadIdx.x >> 7;
    #pragma unroll
    for (int mi = 0; mi < 2; mi++) {
        #pragma unroll
        for (int ni = 0; ni < 4; ni++) {
            int rb = warpM * 32 + mi * 16 + (lane >> 2);
            int cb = nb * 64 + warpN * 32 + ni * 8 + (lane & 3) * 2;
            #pragma unroll
            for (int ci = 0; ci < 4; ci++) {
                int m = rb + ((ci & 2) ? 8 : 0);
                int n = cb + (ci & 1);
                dst[(size_t)m * DM + n] = acc[mi][ni][ci];
            }
        }
    }
}

__global__ void __launch_bounds__(256, 2)
qkv_partial_kernel() {
    extern __shared__ char smraw[];
    GemmSmem* S = (GemmSmem*)smraw;
    const int nb = blockIdx.x, kc = blockIdx.y, z = blockIdx.z;
    const __nv_bfloat16* wh = g_wth + (size_t)z * DM * DM;
    const __nv_bfloat16* wl = g_wtl + (size_t)z * DM * DM;
    float acc[2][4][4] = {};
    gemm_core(g_xh, g_xl, wh, wl, S, acc, nb, kc * 256);
    store_partial(acc, g_part + (size_t)(z * 8 + kc) * MR * DM, nb);
}

__global__ void __launch_bounds__(256)
qkv_reduce_kernel(const float* __restrict__ bq, const float* __restrict__ bk,
                  const float* __restrict__ bv) {
    const int z = blockIdx.y;
    const int idx4 = (blockIdx.x * 256 + threadIdx.x) * 4;
    const int m = idx4 >> 11, n = idx4 & 2047;
    float4 s = make_float4(0.f, 0.f, 0.f, 0.f);
    #pragma unroll
    for (int kc = 0; kc < 8; kc++) {
        float4 p = *reinterpret_cast<const float4*>(&g_part[(size_t)(z * 8 + kc) * MR * DM + idx4]);
        s.x += p.x; s.y += p.y; s.z += p.z; s.w += p.w;
    }
    const int qidx = (((m >> 4) * NH + (n >> 7)) * SNEW + (m & 15)) * HD + (n & 127);
    if (z == 0) {
        s.x = (s.x + bq[n]) * QSCALE;     s.y = (s.y + bq[n + 1]) * QSCALE;
        s.z = (s.z + bq[n + 2]) * QSCALE; s.w = (s.w + bq[n + 3]) * QSCALE;
        uint32_t h0, l0, h1, l1;
        split_pack_rn(s.x, s.y, &h0, &l0);
        split_pack_rn(s.z, s.w, &h1, &l1);
        *reinterpret_cast<uint2*>(&g_qh[qidx]) = make_uint2(h0, h1);
        *reinterpret_cast<uint2*>(&g_ql[qidx]) = make_uint2(l0, l1);
    } else if (z == 1) {
        float4 r = make_float4(s.x + bk[n], s.y + bk[n + 1], s.z + bk[n + 2], s.w + bk[n + 3]);
        *reinterpret_cast<float4*>(&g_knew[qidx]) = r;
    } else {
        float4 r = make_float4(s.x + bv[n], s.y + bv[n + 1], s.z + bv[n + 2], s.w + bv[n + 3]);
        *reinterpret_cast<float4*>(&g_vnew[qidx]) = r;
    }
}

__global__ void __launch_bounds__(256, 2)
o_partial_kernel() {
    extern __shared__ char smraw[];
    GemmSmem* S = (GemmSmem*)smraw;
    const int nb = blockIdx.x, kc = blockIdx.y;
    const __nv_bfloat16* wh = g_wth + (size_t)3 * DM * DM;
    const __nv_bfloat16* wl = g_wtl + (size_t)3 * DM * DM;
    float acc[2][4][4] = {};
    gemm_core(g_oh, g_ol, wh, wl, S, acc, nb, kc * 256);
    store_partial(acc, g_part + (size_t)kc * MR * DM, nb);
}

__global__ void __launch_bounds__(256)
o_reduce_kernel(const float* __restrict__ bo, float* __restrict__ out) {
    const int idx4 = (blockIdx.x * 256 + threadIdx.x) * 4;
    const int n = idx4 & 2047;
    float4 s = make_float4(0.f, 0.f, 0.f, 0.f);
    #pragma unroll
    for (int kc = 0; kc < 8; kc++) {
        float4 p = *reinterpret_cast<const float4*>(&g_part[(size_t)kc * MR * DM + idx4]);
        s.x += p.x; s.y += p.y; s.z += p.z; s.w += p.w;
    }
    float4 r = make_float4(s.x + bo[n], s.y + bo[n + 1], s.z + bo[n + 2], s.w + bo[n + 3]);
    *reinterpret_cast<float4*>(&out[idx4]) = r;
}

// ---------------------------------------------------------------------------
// Attention: one CTA per (b,h). Flash online softmax over 65 key tiles.
// 3-stage cp.async staging; K/V fragments converted fp32->bf16 hi/lo
// DIRECTLY into MMA registers (each element consumed by exactly one thread).
// Skewed per-array swizzles make writes + frag reads bank-conflict-free.
// ---------------------------------------------------------------------------
#define VP 72
struct AttnSmem {
    float stK[3][64 * HD];
    float stV[3][64 * HD];
    float Ss[SNEW * 68];
    __nv_bfloat16 Ph[SNEW * VP], Pl[SNEW * VP];
    float mrow[SNEW], lrow[SNEW], arow[SNEW];
};

// stK: chunk skew 2*key  -> conflict-free for float2 frag reads (keys consecutive)
__device__ __forceinline__ int kaddr(int key, int d) {
    return key * 128 + (((d >> 2) + 2 * key) & 31) * 4 + (d & 3);
}
// stV: chunk skew key    -> conflict-free for scalar transposed reads (keys even-spaced)
__device__ __forceinline__ int vaddr(int key, int d) {
    return key * 128 + (((d >> 2) + key) & 31) * 4 + (d & 3);
}

__global__ void __launch_bounds__(256, 1)
attn_kernel(const float* __restrict__ kc, const float* __restrict__ vc) {
    extern __shared__ char smraw[];
    AttnSmem* S = (AttnSmem*)smraw;
    const int bh = blockIdx.x;
    const int tid = threadIdx.x, lane = tid & 31, wid = tid >> 5;
    const int r = lane >> 2, c2 = (lane & 3) * 2;

    const float* kbase = kc + (size_t)bh * PAST * HD;
    const float* vbase = vc + (size_t)bh * PAST * HD;
    const float* knew  = g_knew + (size_t)bh * SNEW * HD;
    const float* vnew  = g_vnew + (size_t)bh * SNEW * HD;

    if (tid < SNEW) { S->mrow[tid] = -1e30f; S->lrow[tid] = 0.f; }

    // hoist Q fragments into registers (loop-invariant across tiles)
    uint32_t qfh[8][4], qfl[8][4];
    {
        const __nv_bfloat16* qhp = g_qh + (size_t)bh * SNEW * HD;
        const __nv_bfloat16* qlp = g_ql + (size_t)bh * SNEW * HD;
        #pragma unroll
        for (int ks = 0; ks < 8; ks++) {
            int kk = ks * 16 + c2;
            qfh[ks][0] = ldu32(&qhp[r * HD + kk]);
            qfh[ks][1] = ldu32(&qhp[(r + 8) * HD + kk]);
            qfh[ks][2] = ldu32(&qhp[r * HD + kk + 8]);
            qfh[ks][3] = ldu32(&qhp[(r + 8) * HD + kk + 8]);
            qfl[ks][0] = ldu32(&qlp[r * HD + kk]);
            qfl[ks][1] = ldu32(&qlp[(r + 8) * HD + kk]);
            qfl[ks][2] = ldu32(&qlp[r * HD + kk + 8]);
            qfl[ks][3] = ldu32(&qlp[(r + 8) * HD + kk + 8]);
        }
    }

    float o[2][4] = {};

    auto loadKV = [&](int ti, int buf) {
        const float* kp; const float* vp; int nchunk;
        if (ti < 64) { kp = kbase + (size_t)ti * 64 * HD; vp = vbase + (size_t)ti * 64 * HD; nchunk = 64 * 32; }
        else         { kp = knew; vp = vnew; nchunk = SNEW * 32; }
        #pragma unroll
        for (int i = 0; i < 8; i++) {
            int idx = i * 256 + tid;
            if (idx < nchunk) {
                int key = idx >> 5, dg = idx & 31;
                cp16(&S->stK[buf][key * 128 + (((dg + 2 * key) & 31) << 2)], kp + key * 128 + dg * 4);
                cp16(&S->stV[buf][key * 128 + (((dg + key) & 31) << 2)],     vp + key * 128 + dg * 4);
            }
        }
    };

    const int NT = 65;
    loadKV(0, 0); cpcommit();
    loadKV(1, 1); cpcommit();

    for (int ti = 0; ti < NT; ti++) {
        const int cur = ti % 3;
        if (ti + 2 < NT) { loadKV(ti + 2, (ti + 2) % 3); cpcommit(); cpwait<2>(); }
        else if (ti + 1 < NT) { cpwait<1>(); }
        else { cpwait<0>(); }
        __syncthreads();

        const int nk = (ti < 64) ? 64 : SNEW;
        const float* stk = S->stK[cur];
        const float* stv = S->stV[cur];

        // ---- K fragment convert: fp32 staging -> bf16 hi/lo registers ----
        uint32_t kbh[8][2], kbl[8][2];
        {
            const int n = wid * 8 + r;
            const bool ok = (n < nk);
            #pragma unroll
            for (int ks = 0; ks < 8; ks++) {
                int d0 = ks * 16 + c2;
                float2 fa = *reinterpret_cast<const float2*>(&stk[kaddr(n, d0)]);
                float2 fb = *reinterpret_cast<const float2*>(&stk[kaddr(n, d0 + 8)]);
                if (!ok) { fa.x = fa.y = fb.x = fb.y = 0.f; }
                split_pack_rz(fa.x, fa.y, &kbh[ks][0], &kbl[ks][0]);
                split_pack_rz(fb.x, fb.y, &kbh[ks][1], &kbl[ks][1]);
            }
        }
        // ---- V fragment convert (transposed reads) ----
        uint32_t vbh[4][2][2], vbl[4][2][2];
        #pragma unroll
        for (int ks = 0; ks < 4; ks++) {
            int k0 = ks * 16 + c2;
            #pragma unroll
            for (int ni = 0; ni < 2; ni++) {
                int drow = wid * 16 + ni * 8 + r;
                float f0 = stv[vaddr(k0,     drow)];
                float f1 = stv[vaddr(k0 + 1, drow)];
                if (k0 >= nk) { f0 = f1 = 0.f; }
                split_pack_rz(f0, f1, &vbh[ks][ni][0], &vbl[ks][ni][0]);
                float f2 = stv[vaddr(k0 + 8, drow)];
                float f3 = stv[vaddr(k0 + 9, drow)];
                if (k0 + 8 >= nk) { f2 = f3 = 0.f; }
                split_pack_rz(f2, f3, &vbh[ks][ni][1], &vbl[ks][ni][1]);
            }
        }

        // ---- QK^T: warp w -> score columns [8w, 8w+8) ----
        {
            float sacc[4] = {0.f, 0.f, 0.f, 0.f};
            #pragma unroll
            for (int ks = 0; ks < 8; ks++) {
                mmabf(sacc, qfh[ks], kbh[ks]);
                mmabf(sacc, qfh[ks], kbl[ks]);
                mmabf(sacc, qfl[ks], kbh[ks]);
            }
            #pragma unroll
            for (int ci = 0; ci < 4; ci++) {
                int row = r + ((ci & 2) ? 8 : 0);
                int col = wid * 8 + c2 + (ci & 1);
                float v = sacc[ci];
                if (ti == 64 && (col > row || col >= SNEW)) v = -1e30f;
                S->Ss[row * 68 + col] = v;
            }
        }
        __syncthreads();

        // ---- online softmax: one row per half-warp (16 rows in parallel) ----
        {
            const int half = lane >> 4, l4 = lane & 15;
            const int row = wid * 2 + half;
            float4 sv = *reinterpret_cast<const float4*>(&S->Ss[row * 68 + l4 * 4]);
            float mx = fmaxf(fmaxf(sv.x, sv.y), fmaxf(sv.z, sv.w));
            #pragma unroll
            for (int off = 8; off > 0; off >>= 1)
                mx = fmaxf(mx, __shfl_xor_sync(0xffffffffu, mx, off));
            float m_old = S->mrow[row];
            float m_new = fmaxf(m_old, mx);
            float p0 = __expf(sv.x - m_new), p1 = __expf(sv.y - m_new);
            float p2 = __expf(sv.z - m_new), p3 = __expf(sv.w - m_new);
            float ps = (p0 + p1) + (p2 + p3);
            #pragma unroll
            for (int off = 8; off > 0; off >>= 1)
                ps += __shfl_xor_sync(0xffffffffu, ps, off);
            if (l4 == 0) {
                float alpha = __expf(m_old - m_new);
                S->arow[row] = alpha;
                S->lrow[row] = S->lrow[row] * alpha + ps;
                S->mrow[row] = m_new;
            }
            uint32_t hp, lp;
            split_pack_rz(p0, p1, &hp, &lp);
            *reinterpret_cast<uint32_t*>(&S->Ph[row * VP + l4 * 4]) = hp;
            *reinterpret_cast<uint32_t*>(&S->Pl[row * VP + l4 * 4]) = lp;
            split_pack_rz(p2, p3, &hp, &lp);
            *reinterpret_cast<uint32_t*>(&S->Ph[row * VP + l4 * 4 + 2]) = hp;
            *reinterpret_cast<uint32_t*>(&S->Pl[row * VP + l4 * 4 + 2]) = lp;
        }
        __syncthreads();

        // ---- rescale O, then PV: warp w -> d columns [16w, 16w+16) ----
        {
            float a0 = S->arow[r], a1 = S->arow[r + 8];
            #pragma unroll
            for (int ni = 0; ni < 2; ni++) {
                o[ni][0] *= a0; o[ni][1] *= a0;
                o[ni][2] *= a1; o[ni][3] *= a1;
            }
            #pragma unroll
            for (int ks = 0; ks < 4; ks++) {
                int kk = ks * 16 + c2;
                uint32_t ah[4], al[4];
                ah[0] = ldu32(&S->Ph[r * VP + kk]);       ah[1] = ldu32(&S->Ph[(r + 8) * VP + kk]);
                ah[2] = ldu32(&S->Ph[r * VP + kk + 8]);   ah[3] = ldu32(&S->Ph[(r + 8) * VP + kk + 8]);
                al[0] = ldu32(&S->Pl[r * VP + kk]);       al[1] = ldu32(&S->Pl[(r + 8) * VP + kk]);
                al[2] = ldu32(&S->Pl[r * VP + kk + 8]);   al[3] = ldu32(&S->Pl[(r + 8) * VP + kk + 8]);
                #pragma unroll
                for (int ni = 0; ni < 2; ni++) {
                    mmabf(o[ni], ah, vbh[ks][ni]);
                    mmabf(o[ni], ah, vbl[ks][ni]);
                    mmabf(o[ni], al, vbh[ks][ni]);
                }
            }
        }
    }
    __syncthreads();

    // epilogue: normalize, split to bf16 hi/lo, write g_oh/g_ol
    {
        const int b = bh >> 4, h = bh & 15;
        float li0 = 1.f / S->lrow[r], li1 = 1.f / S->lrow[r + 8];
        #pragma unroll
        for (int ni = 0; ni < 2; ni++) {
            #pragma unroll
            for (int p2 = 0; p2 < 2; p2++) {
                int row = r + (p2 ? 8 : 0);
                float li = p2 ? li1 : li0;
                float v0 = o[ni][p2 * 2 + 0] * li;
                float v1 = o[ni][p2 * 2 + 1] * li;
                int col = wid * 16 + ni * 8 + c2;
                size_t oidx = (size_t)(b * SNEW + row) * DM + h * HD + col;
                uint32_t hp, lp;
                split_pack_rn(v0, v1, &hp, &lp);
                *reinterpret_cast<uint32_t*>(&g_oh[oidx]) = hp;
                *reinterpret_cast<uint32_t*>(&g_ol[oidx]) = lp;
            }
        }
    }
}

// ---------------------------------------------------------------------------
extern "C" void kernel_launch(void* const* d_in, const int* in_sizes, int n_in,
                              void* d_out, int out_size) {
    const float* x      = (const float*)d_in[0];
    const float* kcache = (const float*)d_in[1];
    const float* vcache = (const float*)d_in[2];
    const float* Wq = (const float*)d_in[3];
    const float* bq = (const float*)d_in[4];
    const float* Wk = (const float*)d_in[5];
    const float* bk = (const float*)d_in[6];
    const float* Wv = (const float*)d_in[7];
    const float* bv = (const float*)d_in[8];
    const float* Wo = (const float*)d_in[9];
    const float* bo = (const float*)d_in[10];
    float* out = (float*)d_out;

    cudaFuncSetAttribute(qkv_partial_kernel, cudaFuncAttributeMaxDynamicSharedMemorySize, (int)sizeof(GemmSmem));
    cudaFuncSetAttribute(o_partial_kernel,   cudaFuncAttributeMaxDynamicSharedMemorySize, (int)sizeof(GemmSmem));
    cudaFuncSetAttribute(attn_kernel,        cudaFuncAttributeMaxDynamicSharedMemorySize, (int)sizeof(AttnSmem));

    dim3 gw(32, 32, 4);
    prep_w_kernel<<<gw, 256>>>(Wq, Wk, Wv, Wo);
    prep_x_kernel<<<512, 256>>>(x);
    dim3 gq(32, 8, 3);
    qkv_partial_kernel<<<gq, 256, sizeof(GemmSmem)>>>();
    dim3 gr(256, 3);
    qkv_reduce_kernel<<<gr, 256>>>(bq, bk, bv);
    attn_kernel<<<128, 256, sizeof(AttnSmem)>>>(kcache, vcache);
    dim3 go(32, 8);
    o_partial_kernel<<<go, 256, sizeof(GemmSmem)>>>();
    o_reduce_kernel<<<256, 256>>>(bo, out);
}

// round 17
// speedup vs baseline: 2.3365x; 1.1277x over previous
#include <cuda_runtime.h>
#include <cuda_bf16.h>
#include <stdint.h>

#define NB      8
#define SNEW    16
#define DM      2048
#define NH      16
#define HD      128
#define PAST    4096
#define MR      128
#define QSCALE  0.08838834764831843f

// ---------------- device scratch ----------------
__device__ __nv_bfloat16 g_xh[MR * DM], g_xl[MR * DM];          // x split
__device__ __nv_bfloat16 g_qh[MR * DM], g_ql[MR * DM];          // Q (scaled) split
__device__ float         g_knew[MR * DM], g_vnew[MR * DM];
__device__ __nv_bfloat16 g_oh[MR * DM], g_ol[MR * DM];          // attn out split
__device__ float         g_part[3 * 8 * MR * DM];               // split-K partials

// ---------------- helpers ----------------
__device__ __forceinline__ void cp16(void* s, const void* g) {
    uint32_t sa = (uint32_t)__cvta_generic_to_shared(s);
    asm volatile("cp.async.cg.shared.global [%0], [%1], 16;\n" :: "r"(sa), "l"(g));
}
__device__ __forceinline__ void cpcommit() { asm volatile("cp.async.commit_group;\n"); }
template <int N>
__device__ __forceinline__ void cpwait() { asm volatile("cp.async.wait_group %0;\n" :: "n"(N)); }

__device__ __forceinline__ void mmabf(float* c, const uint32_t* a, const uint32_t* b) {
    asm volatile(
        "mma.sync.aligned.m16n8k16.row.col.f32.bf16.bf16.f32 "
        "{%0,%1,%2,%3},{%4,%5,%6,%7},{%8,%9},{%0,%1,%2,%3};"
        : "+f"(c[0]), "+f"(c[1]), "+f"(c[2]), "+f"(c[3])
        : "r"(a[0]), "r"(a[1]), "r"(a[2]), "r"(a[3]), "r"(b[0]), "r"(b[1]));
}
__device__ __forceinline__ uint32_t ldu32(const __nv_bfloat16* p) {
    return *reinterpret_cast<const uint32_t*>(p);
}
__device__ __forceinline__ void split2(float f, __nv_bfloat16* hp, __nv_bfloat16* lp) {
    __nv_bfloat16 h = __float2bfloat16(f);
    *hp = h;
    *lp = __float2bfloat16(f - __bfloat162float(h));
}
// rn split of a pair -> packed u32 hi, packed u32 lo
__device__ __forceinline__ void split_pack_rn(float f0, float f1, uint32_t* hp, uint32_t* lp) {
    __nv_bfloat16 h0, l0, h1, l1;
    split2(f0, &h0, &l0); split2(f1, &h1, &l1);
    uint16_t a0 = *reinterpret_cast<uint16_t*>(&h0), a1 = *reinterpret_cast<uint16_t*>(&h1);
    uint16_t b0 = *reinterpret_cast<uint16_t*>(&l0), b1 = *reinterpret_cast<uint16_t*>(&l1);
    *hp = (uint32_t)a0 | ((uint32_t)a1 << 16);
    *lp = (uint32_t)b0 | ((uint32_t)b1 << 16);
}
// rz (truncate) split of a pair: hi via PRMT, lo via cvt.bf16x2
__device__ __forceinline__ void split_pack_rz(float f0, float f1, uint32_t* hp, uint32_t* lp) {
    uint32_t b0 = __float_as_uint(f0), b1 = __float_as_uint(f1);
    *hp = __byte_perm(b0, b1, 0x7632);
    float lo0 = f0 - __uint_as_float(b0 & 0xFFFF0000u);
    float lo1 = f1 - __uint_as_float(b1 & 0xFFFF0000u);
    uint32_t lp2;
    asm("cvt.rn.bf16x2.f32 %0, %1, %2;" : "=r"(lp2) : "f"(lo1), "f"(lo0));
    *lp = lp2;
}

// ---------------------------------------------------------------------------
// Prep: x -> bf16 hi/lo (A operand is shared across warps -> pre-split)
// ---------------------------------------------------------------------------
__global__ void __launch_bounds__(256)
prep_x_kernel(const float* __restrict__ x) {
    int idx2 = (blockIdx.x * 256 + threadIdx.x) * 2;
    float2 f = *reinterpret_cast<const float2*>(&x[idx2]);
    uint32_t hp, lp;
    split_pack_rn(f.x, f.y, &hp, &lp);
    *reinterpret_cast<uint32_t*>(&g_xh[idx2]) = hp;
    *reinterpret_cast<uint32_t*>(&g_xl[idx2]) = lp;
}

// ---------------------------------------------------------------------------
// Split-K GEMM partial. A: pre-split bf16 (pitch-72 smem). B: RAW fp32 W tile
// staged with a skewed swizzle; each thread rz-splits its transposed
// B-fragments directly into MMA registers (each W element used by exactly one
// thread). BK=64, 4 iters/CTA, 2 CTAs/SM (104 KB smem).
// ---------------------------------------------------------------------------
#define AP 72
struct GemmSmem {
    __nv_bfloat16 Ah[2][MR * AP], Al[2][MR * AP];   // 72 KB
    float stB[2][64 * 64];                          // 32 KB
};

// W staging: row k (64 floats), chunk skew k -> transposed frag reads
// (fixed n, k varying by lane) hit 32 distinct banks.
__device__ __forceinline__ int waddr(int k, int n) {
    return k * 64 + (((n >> 2) + k) & 15) * 4 + (n & 3);
}

__device__ __forceinline__ void gemm_stage(GemmSmem* S, int st,
                                           const __nv_bfloat16* Ahp, const __nv_bfloat16* Alp,
                                           const float* W,
                                           int nb, int kbase) {
    const int tid = threadIdx.x;
    #pragma unroll
    for (int i = 0; i < 4; i++) {
        int idx = tid + i * 256; int r = idx >> 3, c = (idx & 7) * 8;
        cp16(&S->Ah[st][r * AP + c], Ahp + (size_t)r * DM + kbase + c);
        cp16(&S->Al[st][r * AP + c], Alp + (size_t)r * DM + kbase + c);
    }
    #pragma unroll
    for (int i = 0; i < 4; i++) {
        int idx = tid + i * 256; int k = idx >> 4, cg = idx & 15;
        cp16(&S->stB[st][k * 64 + (((cg + k) & 15) << 2)],
             W + (size_t)(kbase + k) * DM + nb * 64 + cg * 4);
    }
}

__device__ __forceinline__ void gemm_core(const __nv_bfloat16* Ahp, const __nv_bfloat16* Alp,
                                          const float* W,
                                          GemmSmem* S, float acc[2][4][4], int nb, int k0) {
    const int tid = threadIdx.x, lane = tid & 31;
    const int warpM = (tid >> 5) & 3, warpN = tid >> 7;

    gemm_stage(S, 0, Ahp, Alp, W, nb, k0);
    cpcommit();

    #pragma unroll 1
    for (int kt = 0; kt < 4; kt++) {
        int cur = kt & 1;
        if (kt < 3) {
            gemm_stage(S, cur ^ 1, Ahp, Alp, W, nb, k0 + (kt + 1) * 64);
            cpcommit();
            cpwait<1>();
        } else {
            cpwait<0>();
        }
        __syncthreads();

        const float* stb = S->stB[cur];
        #pragma unroll
        for (int ks = 0; ks < 4; ks++) {
            const int kk = ks * 16 + (lane & 3) * 2, r0 = lane >> 2;
            uint32_t ah[2][4], al[2][4];
            #pragma unroll
            for (int mi = 0; mi < 2; mi++) {
                int r = warpM * 32 + mi * 16 + r0;
                ah[mi][0] = ldu32(&S->Ah[cur][r * AP + kk]);
                ah[mi][1] = ldu32(&S->Ah[cur][(r + 8) * AP + kk]);
                ah[mi][2] = ldu32(&S->Ah[cur][r * AP + kk + 8]);
                ah[mi][3] = ldu32(&S->Ah[cur][(r + 8) * AP + kk + 8]);
                al[mi][0] = ldu32(&S->Al[cur][r * AP + kk]);
                al[mi][1] = ldu32(&S->Al[cur][(r + 8) * AP + kk]);
                al[mi][2] = ldu32(&S->Al[cur][r * AP + kk + 8]);
                al[mi][3] = ldu32(&S->Al[cur][(r + 8) * AP + kk + 8]);
            }
            #pragma unroll
            for (int ni = 0; ni < 4; ni++) {
                int n = warpN * 32 + ni * 8 + r0;
                uint32_t bh[2], bl[2];
                float f0 = stb[waddr(kk,     n)];
                float f1 = stb[waddr(kk + 1, n)];
                split_pack_rz(f0, f1, &bh[0], &bl[0]);
                float f2 = stb[waddr(kk + 8, n)];
                float f3 = stb[waddr(kk + 9, n)];
                split_pack_rz(f2, f3, &bh[1], &bl[1]);
                #pragma unroll
                for (int mi = 0; mi < 2; mi++) {
                    mmabf(acc[mi][ni], ah[mi], bh);
                    mmabf(acc[mi][ni], ah[mi], bl);
                    mmabf(acc[mi][ni], al[mi], bh);
                }
            }
        }
        __syncthreads();
    }
}

__device__ __forceinline__ void store_partial(float acc[2][4][4], float* dst, int nb) {
    const int lane = threadIdx.x & 31, warpM = (threadIdx.x >> 5) & 3, warpN = threadIdx.x >> 7;
    #pragma unroll
    for (int mi = 0; mi < 2; mi++) {
        #pragma unroll
        for (int ni = 0; ni < 4; ni++) {
            int rb = warpM * 32 + mi * 16 + (lane >> 2);
            int cb = nb * 64 + warpN * 32 + ni * 8 + (lane & 3) * 2;
            #pragma unroll
            for (int ci = 0; ci < 4; ci++) {
                int m = rb + ((ci & 2) ? 8 : 0);
                int n = cb + (ci & 1);
                dst[(size_t)m * DM + n] = acc[mi][ni][ci];
            }
        }
    }
}

__global__ void __launch_bounds__(256, 2)
qkv_partial_kernel(const float* __restrict__ Wq, const float* __restrict__ Wk,
                   const float* __restrict__ Wv) {
    extern __shared__ char smraw[];
    GemmSmem* S = (GemmSmem*)smraw;
    const int nb = blockIdx.x, kc = blockIdx.y, z = blockIdx.z;
    const float* W = (z == 0) ? Wq : ((z == 1) ? Wk : Wv);
    float acc[2][4][4] = {};
    gemm_core(g_xh, g_xl, W, S, acc, nb, kc * 256);
    store_partial(acc, g_part + (size_t)(z * 8 + kc) * MR * DM, nb);
}

__global__ void __launch_bounds__(256)
qkv_reduce_kernel(const float* __restrict__ bq, const float* __restrict__ bk,
                  const float* __restrict__ bv) {
    const int z = blockIdx.y;
    const int idx4 = (blockIdx.x * 256 + threadIdx.x) * 4;
    const int m = idx4 >> 11, n = idx4 & 2047;
    float4 s = make_float4(0.f, 0.f, 0.f, 0.f);
    #pragma unroll
    for (int kc = 0; kc < 8; kc++) {
        float4 p = *reinterpret_cast<const float4*>(&g_part[(size_t)(z * 8 + kc) * MR * DM + idx4]);
        s.x += p.x; s.y += p.y; s.z += p.z; s.w += p.w;
    }
    const int qidx = (((m >> 4) * NH + (n >> 7)) * SNEW + (m & 15)) * HD + (n & 127);
    if (z == 0) {
        s.x = (s.x + bq[n]) * QSCALE;     s.y = (s.y + bq[n + 1]) * QSCALE;
        s.z = (s.z + bq[n + 2]) * QSCALE; s.w = (s.w + bq[n + 3]) * QSCALE;
        uint32_t h0, l0, h1, l1;
        split_pack_rn(s.x, s.y, &h0, &l0);
        split_pack_rn(s.z, s.w, &h1, &l1);
        *reinterpret_cast<uint2*>(&g_qh[qidx]) = make_uint2(h0, h1);
        *reinterpret_cast<uint2*>(&g_ql[qidx]) = make_uint2(l0, l1);
    } else if (z == 1) {
        float4 r = make_float4(s.x + bk[n], s.y + bk[n + 1], s.z + bk[n + 2], s.w + bk[n + 3]);
        *reinterpret_cast<float4*>(&g_knew[qidx]) = r;
    } else {
        float4 r = make_float4(s.x + bv[n], s.y + bv[n + 1], s.z + bv[n + 2], s.w + bv[n + 3]);
        *reinterpret_cast<float4*>(&g_vnew[qidx]) = r;
    }
}

__global__ void __launch_bounds__(256, 2)
o_partial_kernel(const float* __restrict__ Wo) {
    extern __shared__ char smraw[];
    GemmSmem* S = (GemmSmem*)smraw;
    const int nb = blockIdx.x, kc = blockIdx.y;
    float acc[2][4][4] = {};
    gemm_core(g_oh, g_ol, Wo, S, acc, nb, kc * 256);
    store_partial(acc, g_part + (size_t)kc * MR * DM, nb);
}

__global__ void __launch_bounds__(256)
o_reduce_kernel(const float* __restrict__ bo, float* __restrict__ out) {
    const int idx4 = (blockIdx.x * 256 + threadIdx.x) * 4;
    const int n = idx4 & 2047;
    float4 s = make_float4(0.f, 0.f, 0.f, 0.f);
    #pragma unroll
    for (int kc = 0; kc < 8; kc++) {
        float4 p = *reinterpret_cast<const float4*>(&g_part[(size_t)kc * MR * DM + idx4]);
        s.x += p.x; s.y += p.y; s.z += p.z; s.w += p.w;
    }
    float4 r = make_float4(s.x + bo[n], s.y + bo[n + 1], s.z + bo[n + 2], s.w + bo[n + 3]);
    *reinterpret_cast<float4*>(&out[idx4]) = r;
}

// ---------------------------------------------------------------------------
// Attention: one CTA per (b,h). Flash online softmax over 65 key tiles.
// 3-stage cp.async staging; K/V fragments converted fp32->bf16 hi/lo
// DIRECTLY into MMA registers. (unchanged from R12 — it just won)
// ---------------------------------------------------------------------------
#define VP 72
struct AttnSmem {
    float stK[3][64 * HD];
    float stV[3][64 * HD];
    float Ss[SNEW * 68];
    __nv_bfloat16 Ph[SNEW * VP], Pl[SNEW * VP];
    float mrow[SNEW], lrow[SNEW], arow[SNEW];
};

// stK: chunk skew 2*key  -> conflict-free for float2 frag reads (keys consecutive)
__device__ __forceinline__ int kaddr(int key, int d) {
    return key * 128 + (((d >> 2) + 2 * key) & 31) * 4 + (d & 3);
}
// stV: chunk skew key    -> conflict-free for scalar transposed reads (keys even-spaced)
__device__ __forceinline__ int vaddr(int key, int d) {
    return key * 128 + (((d >> 2) + key) & 31) * 4 + (d & 3);
}

__global__ void __launch_bounds__(256, 1)
attn_kernel(const float* __restrict__ kc, const float* __restrict__ vc) {
    extern __shared__ char smraw[];
    AttnSmem* S = (AttnSmem*)smraw;
    const int bh = blockIdx.x;
    const int tid = threadIdx.x, lane = tid & 31, wid = tid >> 5;
    const int r = lane >> 2, c2 = (lane & 3) * 2;

    const float* kbase = kc + (size_t)bh * PAST * HD;
    const float* vbase = vc + (size_t)bh * PAST * HD;
    const float* knew  = g_knew + (size_t)bh * SNEW * HD;
    const float* vnew  = g_vnew + (size_t)bh * SNEW * HD;

    if (tid < SNEW) { S->mrow[tid] = -1e30f; S->lrow[tid] = 0.f; }

    // hoist Q fragments into registers (loop-invariant across tiles)
    uint32_t qfh[8][4], qfl[8][4];
    {
        const __nv_bfloat16* qhp = g_qh + (size_t)bh * SNEW * HD;
        const __nv_bfloat16* qlp = g_ql + (size_t)bh * SNEW * HD;
        #pragma unroll
        for (int ks = 0; ks < 8; ks++) {
            int kk = ks * 16 + c2;
            qfh[ks][0] = ldu32(&qhp[r * HD + kk]);
            qfh[ks][1] = ldu32(&qhp[(r + 8) * HD + kk]);
            qfh[ks][2] = ldu32(&qhp[r * HD + kk + 8]);
            qfh[ks][3] = ldu32(&qhp[(r + 8) * HD + kk + 8]);
            qfl[ks][0] = ldu32(&qlp[r * HD + kk]);
            qfl[ks][1] = ldu32(&qlp[(r + 8) * HD + kk]);
            qfl[ks][2] = ldu32(&qlp[r * HD + kk + 8]);
            qfl[ks][3] = ldu32(&qlp[(r + 8) * HD + kk + 8]);
        }
    }

    float o[2][4] = {};

    auto loadKV = [&](int ti, int buf) {
        const float* kp; const float* vp; int nchunk;
        if (ti < 64) { kp = kbase + (size_t)ti * 64 * HD; vp = vbase + (size_t)ti * 64 * HD; nchunk = 64 * 32; }
        else         { kp = knew; vp = vnew; nchunk = SNEW * 32; }
        #pragma unroll
        for (int i = 0; i < 8; i++) {
            int idx = i * 256 + tid;
            if (idx < nchunk) {
                int key = idx >> 5, dg = idx & 31;
                cp16(&S->stK[buf][key * 128 + (((dg + 2 * key) & 31) << 2)], kp + key * 128 + dg * 4);
                cp16(&S->stV[buf][key * 128 + (((dg + key) & 31) << 2)],     vp + key * 128 + dg * 4);
            }
        }
    };

    const int NT = 65;
    loadKV(0, 0); cpcommit();
    loadKV(1, 1); cpcommit();

    for (int ti = 0; ti < NT; ti++) {
        const int cur = ti % 3;
        if (ti + 2 < NT) { loadKV(ti + 2, (ti + 2) % 3); cpcommit(); cpwait<2>(); }
        else if (ti + 1 < NT) { cpwait<1>(); }
        else { cpwait<0>(); }
        __syncthreads();

        const int nk = (ti < 64) ? 64 : SNEW;
        const float* stk = S->stK[cur];
        const float* stv = S->stV[cur];

        // ---- K fragment convert: fp32 staging -> bf16 hi/lo registers ----
        uint32_t kbh[8][2], kbl[8][2];
        {
            const int n = wid * 8 + r;
            const bool ok = (n < nk);
            #pragma unroll
            for (int ks = 0; ks < 8; ks++) {
                int d0 = ks * 16 + c2;
                float2 fa = *reinterpret_cast<const float2*>(&stk[kaddr(n, d0)]);
                float2 fb = *reinterpret_cast<const float2*>(&stk[kaddr(n, d0 + 8)]);
                if (!ok) { fa.x = fa.y = fb.x = fb.y = 0.f; }
                split_pack_rz(fa.x, fa.y, &kbh[ks][0], &kbl[ks][0]);
                split_pack_rz(fb.x, fb.y, &kbh[ks][1], &kbl[ks][1]);
            }
        }
        // ---- V fragment convert (transposed reads) ----
        uint32_t vbh[4][2][2], vbl[4][2][2];
        #pragma unroll
        for (int ks = 0; ks < 4; ks++) {
            int k0 = ks * 16 + c2;
            #pragma unroll
            for (int ni = 0; ni < 2; ni++) {
                int drow = wid * 16 + ni * 8 + r;
                float f0 = stv[vaddr(k0,     drow)];
                float f1 = stv[vaddr(k0 + 1, drow)];
                if (k0 >= nk) { f0 = f1 = 0.f; }
                split_pack_rz(f0, f1, &vbh[ks][ni][0], &vbl[ks][ni][0]);
                float f2 = stv[vaddr(k0 + 8, drow)];
                float f3 = stv[vaddr(k0 + 9, drow)];
                if (k0 + 8 >= nk) { f2 = f3 = 0.f; }
                split_pack_rz(f2, f3, &vbh[ks][ni][1], &vbl[ks][ni][1]);
            }
        }

        // ---- QK^T: warp w -> score columns [8w, 8w+8) ----
        {
            float sacc[4] = {0.f, 0.f, 0.f, 0.f};
            #pragma unroll
            for (int ks = 0; ks < 8; ks++) {
                mmabf(sacc, qfh[ks], kbh[ks]);
                mmabf(sacc, qfh[ks], kbl[ks]);
                mmabf(sacc, qfl[ks], kbh[ks]);
            }
            #pragma unroll
            for (int ci = 0; ci < 4; ci++) {
                int row = r + ((ci & 2) ? 8 : 0);
                int col = wid * 8 + c2 + (ci & 1);
                float v = sacc[ci];
                if (ti == 64 && (col > row || col >= SNEW)) v = -1e30f;
                S->Ss[row * 68 + col] = v;
            }
        }
        __syncthreads();

        // ---- online softmax: one row per half-warp (16 rows in parallel) ----
        {
            const int half = lane >> 4, l4 = lane & 15;
            const int row = wid * 2 + half;
            float4 sv = *reinterpret_cast<const float4*>(&S->Ss[row * 68 + l4 * 4]);
            float mx = fmaxf(fmaxf(sv.x, sv.y), fmaxf(sv.z, sv.w));
            #pragma unroll
            for (int off = 8; off > 0; off >>= 1)
                mx = fmaxf(mx, __shfl_xor_sync(0xffffffffu, mx, off));
            float m_old = S->mrow[row];
            float m_new = fmaxf(m_old, mx);
            float p0 = __expf(sv.x - m_new), p1 = __expf(sv.y - m_new);
            float p2 = __expf(sv.z - m_new), p3 = __expf(sv.w - m_new);
            float ps = (p0 + p1) + (p2 + p3);
            #pragma unroll
            for (int off = 8; off > 0; off >>= 1)
                ps += __shfl_xor_sync(0xffffffffu, ps, off);
            if (l4 == 0) {
                float alpha = __expf(m_old - m_new);
                S->arow[row] = alpha;
                S->lrow[row] = S->lrow[row] * alpha + ps;
                S->mrow[row] = m_new;
            }
            uint32_t hp, lp;
            split_pack_rz(p0, p1, &hp, &lp);
            *reinterpret_cast<uint32_t*>(&S->Ph[row * VP + l4 * 4]) = hp;
            *reinterpret_cast<uint32_t*>(&S->Pl[row * VP + l4 * 4]) = lp;
            split_pack_rz(p2, p3, &hp, &lp);
            *reinterpret_cast<uint32_t*>(&S->Ph[row * VP + l4 * 4 + 2]) = hp;
            *reinterpret_cast<uint32_t*>(&S->Pl[row * VP + l4 * 4 + 2]) = lp;
        }
        __syncthreads();

        // ---- rescale O, then PV: warp w -> d columns [16w, 16w+16) ----
        {
            float a0 = S->arow[r], a1 = S->arow[r + 8];
            #pragma unroll
            for (int ni = 0; ni < 2; ni++) {
                o[ni][0] *= a0; o[ni][1] *= a0;
                o[ni][2] *= a1; o[ni][3] *= a1;
            }
            #pragma unroll
            for (int ks = 0; ks < 4; ks++) {
                int kk = ks * 16 + c2;
                uint32_t ah[4], al[4];
                ah[0] = ldu32(&S->Ph[r * VP + kk]);       ah[1] = ldu32(&S->Ph[(r + 8) * VP + kk]);
                ah[2] = ldu32(&S->Ph[r * VP + kk + 8]);   ah[3] = ldu32(&S->Ph[(r + 8) * VP + kk + 8]);
                al[0] = ldu32(&S->Pl[r * VP + kk]);       al[1] = ldu32(&S->Pl[(r + 8) * VP + kk]);
                al[2] = ldu32(&S->Pl[r * VP + kk + 8]);   al[3] = ldu32(&S->Pl[(r + 8) * VP + kk + 8]);
                #pragma unroll
                for (int ni = 0; ni < 2; ni++) {
                    mmabf(o[ni], ah, vbh[ks][ni]);
                    mmabf(o[ni], ah, vbl[ks][ni]);
                    mmabf(o[ni], al, vbh[ks][ni]);
                }
            }
        }
    }
    __syncthreads();

    // epilogue: normalize, split to bf16 hi/lo, write g_oh/g_ol
    {
        const int b = bh >> 4, h = bh & 15;
        float li0 = 1.f / S->lrow[r], li1 = 1.f / S->lrow[r + 8];
        #pragma unroll
        for (int ni = 0; ni < 2; ni++) {
            #pragma unroll
            for (int p2 = 0; p2 < 2; p2++) {
                int row = r + (p2 ? 8 : 0);
                float li = p2 ? li1 : li0;
                float v0 = o[ni][p2 * 2 + 0] * li;
                float v1 = o[ni][p2 * 2 + 1] * li;
                int col = wid * 16 + ni * 8 + c2;
                size_t oidx = (size_t)(b * SNEW + row) * DM + h * HD + col;
                uint32_t hp, lp;
                split_pack_rn(v0, v1, &hp, &lp);
                *reinterpret_cast<uint32_t*>(&g_oh[oidx]) = hp;
                *reinterpret_cast<uint32_t*>(&g_ol[oidx]) = lp;
            }
        }
    }
}

// ---------------------------------------------------------------------------
extern "C" void kernel_launch(void* const* d_in, const int* in_sizes, int n_in,
                              void* d_out, int out_size) {
    const float* x      = (const float*)d_in[0];
    const float* kcache = (const float*)d_in[1];
    const float* vcache = (const float*)d_in[2];
    const float* Wq = (const float*)d_in[3];
    const float* bq = (const float*)d_in[4];
    const float* Wk = (const float*)d_in[5];
    const float* bk = (const float*)d_in[6];
    const float* Wv = (const float*)d_in[7];
    const float* bv = (const float*)d_in[8];
    const float* Wo = (const float*)d_in[9];
    const float* bo = (const float*)d_in[10];
    float* out = (float*)d_out;

    cudaFuncSetAttribute(qkv_partial_kernel, cudaFuncAttributeMaxDynamicSharedMemorySize, (int)sizeof(GemmSmem));
    cudaFuncSetAttribute(o_partial_kernel,   cudaFuncAttributeMaxDynamicSharedMemorySize, (int)sizeof(GemmSmem));
    cudaFuncSetAttribute(attn_kernel,        cudaFuncAttributeMaxDynamicSharedMemorySize, (int)sizeof(AttnSmem));

    prep_x_kernel<<<512, 256>>>(x);
    dim3 gq(32, 8, 3);
    qkv_partial_kernel<<<gq, 256, sizeof(GemmSmem)>>>(Wq, Wk, Wv);
    dim3 gr(256, 3);
    qkv_reduce_kernel<<<gr, 256>>>(bq, bk, bv);
    attn_kernel<<<128, 256, sizeof(AttnSmem)>>>(kcache, vcache);
    dim3 go(32, 8);
    o_partial_kernel<<<go, 256, sizeof(GemmSmem)>>>(Wo);
    o_reduce_kernel<<<256, 256>>>(bo, out);
}